// round 13
// baseline (speedup 1.0000x reference)
#include <cuda_runtime.h>
#include <math.h>
#include <stdint.h>

// Problem constants
#define Bsz 8
#define Cch 512
#define Ls 4096
#define Gg 4
#define Dd 128
#define Mrows 32768   // B*L

// ---------------- scratch (device globals; no cudaMalloc allowed) -------------
__device__ float g_xn  [(size_t)Bsz*Ls*Cch];
__device__ float g_zp  [32*Bsz*Cch];
__device__ float g_gate[Bsz*Cch];
__device__ float g_xz  [(size_t)Gg*Mrows*256];
__device__ float g_u   [(size_t)Gg*Mrows*Dd];
__device__ float g_dA  [(size_t)Gg*Mrows*Dd];
__device__ float g_dbu [(size_t)Gg*Mrows*Dd];
__device__ float g_Cv  [Gg*Mrows];
__device__ float g_P   [Gg*Bsz*64*Dd];
__device__ float g_hc  [Gg*Bsz*64*Dd];
__device__ float g_hin [Gg*Bsz*64*Dd];
__device__ float g_yz  [(size_t)Gg*Mrows*Dd];
__device__ float g_ycat[(size_t)Mrows*Cch];
__device__ float g_xmn [(size_t)Mrows*Cch];
// tf32-rounded weight copies
__device__ float g_ipw [Gg*256*128];
__device__ float g_opw [Gg*128*128];
__device__ float g_pw  [512*512];

// ---------------- helpers -------------------------------------------------------
__device__ __forceinline__ float tf32r(float x) {
    uint32_t u;
    asm("cvt.rna.tf32.f32 %0, %1;" : "=r"(u) : "f"(x));
    return __uint_as_float(u);
}
__device__ __forceinline__ uint32_t sm_u32(const void* p) {
    return (uint32_t)__cvta_generic_to_shared(p);
}
__device__ __forceinline__ void cpa16(uint32_t dst, const float* src) {
    asm volatile("cp.async.cg.shared.global [%0], [%1], 16;" :: "r"(dst), "l"(src));
}
__device__ __forceinline__ void cpa_commit() { asm volatile("cp.async.commit_group;"); }
template<int N> __device__ __forceinline__ void cpa_wait() {
    asm volatile("cp.async.wait_group %0;" :: "n"(N));
}
__device__ __forceinline__ void mma_tf32_16n8k8(float* c, const uint32_t* a, const uint32_t* b) {
    asm volatile(
        "mma.sync.aligned.m16n8k8.row.col.f32.tf32.tf32.f32 "
        "{%0,%1,%2,%3}, {%4,%5,%6,%7}, {%8,%9}, {%0,%1,%2,%3};"
        : "+f"(c[0]), "+f"(c[1]), "+f"(c[2]), "+f"(c[3])
        : "r"(a[0]), "r"(a[1]), "r"(a[2]), "r"(a[3]), "r"(b[0]), "r"(b[1]));
}

// SMEM stage: 128 rows x 16 cols, row pitch 20 floats (conflict-free fragments)
#define SPITCH 20
#define STAGE_FLOATS (128 * SPITCH)

__device__ __forceinline__ void stage_load(const float* __restrict__ g, int ld,
                                           int r0, int k0, float* sbuf, int tid)
{
#pragma unroll
    for (int i = 0; i < 2; i++) {
        int s = tid + (i << 8);          // 0..511
        int r = s >> 2, seg = s & 3;
        cpa16(sm_u32(sbuf + r * SPITCH + seg * 4),
              g + (size_t)(r0 + r) * ld + k0 + seg * 4);
    }
}

// ---------------- tf32 mma.sync 128x128xK core ----------------------------------
template<int S>   // S = K/16 stages
__device__ __forceinline__ void mma_gemm(const float* __restrict__ Ag, int lda,
                                         const float* __restrict__ Bg,
                                         int mBase, int nBase,
                                         float acc[2][8][4],
                                         float* As, float* Bs)
{
    const int KTOT = 16 * S;
    int tid = threadIdx.x, wid = tid >> 5, lane = tid & 31;
    int gid = lane >> 2, tidx = lane & 3;
    int wm = (wid & 3) * 32, wn = (wid >> 2) * 64;

    stage_load(Ag, lda, mBase, 0, As, tid);
    stage_load(Bg, KTOT, nBase, 0, Bs, tid);
    cpa_commit();

    for (int s = 0; s < S; s++) {
        if (s + 1 < S) {
            int nb = (s + 1) & 1;
            stage_load(Ag, lda, mBase, (s + 1) * 16, As + nb * STAGE_FLOATS, tid);
            stage_load(Bg, KTOT, nBase, (s + 1) * 16, Bs + nb * STAGE_FLOATS, tid);
            cpa_commit();
            cpa_wait<1>();
        } else {
            cpa_wait<0>();
        }
        __syncthreads();
        const float* Ab = As + (s & 1) * STAGE_FLOATS;
        const float* Bb = Bs + (s & 1) * STAGE_FLOATS;
#pragma unroll
        for (int kk = 0; kk < 16; kk += 8) {
            uint32_t afr[2][4];
#pragma unroll
            for (int mt = 0; mt < 2; mt++) {
                const float* ap = Ab + (wm + mt * 16 + gid) * SPITCH + kk + tidx;
                afr[mt][0] = __float_as_uint(ap[0]);
                afr[mt][1] = __float_as_uint(ap[8 * SPITCH]);
                afr[mt][2] = __float_as_uint(ap[4]);
                afr[mt][3] = __float_as_uint(ap[8 * SPITCH + 4]);
            }
            uint32_t bfr[8][2];
#pragma unroll
            for (int nt = 0; nt < 8; nt++) {
                const float* bp = Bb + (wn + nt * 8 + gid) * SPITCH + kk + tidx;
                bfr[nt][0] = __float_as_uint(bp[0]);
                bfr[nt][1] = __float_as_uint(bp[4]);
            }
#pragma unroll
            for (int mt = 0; mt < 2; mt++)
#pragma unroll
                for (int nt = 0; nt < 8; nt++)
                    mma_tf32_16n8k8(acc[mt][nt], afr[mt], bfr[nt]);
        }
        __syncthreads();
    }
}

// ---------------- kernel 1: layernorm over C ----------------------------------
__global__ void k_ln1(const float* __restrict__ x,
                      const float* __restrict__ lg, const float* __restrict__ lb)
{
    int b = blockIdx.y;
    int l = blockIdx.x * 128 + threadIdx.x;
    const float* xp = x + (size_t)b * Cch * Ls + l;
    float s = 0.f, s2 = 0.f;
#pragma unroll 8
    for (int c = 0; c < Cch; c++) { float v = xp[(size_t)c * Ls]; s += v; s2 += v * v; }
    float mu = s * (1.f / Cch);
    float rs = rsqrtf(s2 * (1.f / Cch) - mu * mu + 1e-5f);
    float* out = g_xn + ((size_t)b * Ls + l) * Cch;
#pragma unroll 4
    for (int c = 0; c < Cch; c += 4) {
        float4 o;
        o.x = tf32r((xp[(size_t)(c + 0) * Ls] - mu) * rs * lg[c + 0] + lb[c + 0]);
        o.y = tf32r((xp[(size_t)(c + 1) * Ls] - mu) * rs * lg[c + 1] + lb[c + 1]);
        o.z = tf32r((xp[(size_t)(c + 2) * Ls] - mu) * rs * lg[c + 2] + lb[c + 2]);
        o.w = tf32r((xp[(size_t)(c + 3) * Ls] - mu) * rs * lg[c + 3] + lb[c + 3]);
        *(float4*)(out + c) = o;
    }
}

// ---------------- kernel 2: partial column sums -------------------------------
__global__ void k_zsum()
{
    int b = blockIdx.y, k = blockIdx.x, c = threadIdx.x;
    const float* p = g_xn + ((size_t)b * Ls + k * 128) * Cch + c;
    float s = 0.f;
#pragma unroll 8
    for (int i = 0; i < 128; i++) s += p[(size_t)i * Cch];
    g_zp[(k * Bsz + b) * Cch + c] = s;
}

// ---------------- kernel 3: gate MLP — parallel (one block per batch) ----------
__global__ void __launch_bounds__(256) k_gate(const float* __restrict__ fc1w,
                                              const float* __restrict__ fc1b,
                                              const float* __restrict__ fc2w,
                                              const float* __restrict__ fc2b)
{
    __shared__ float zsm[512];
    __shared__ float hsm[32];
    int t = threadIdx.x, b = blockIdx.x;
    int warp = t >> 5, lane = t & 31;
    for (int c = t; c < 512; c += 256) {
        float s = 0.f;
#pragma unroll
        for (int k = 0; k < 32; k++) s += g_zp[(k * Bsz + b) * 512 + c];
        zsm[c] = s * (1.f / Ls);
    }
    __syncthreads();
    for (int r = warp; r < 32; r += 8) {
        float p = 0.f;
#pragma unroll 4
        for (int i = lane; i < 512; i += 32) p += zsm[i] * fc1w[r * 512 + i];
#pragma unroll
        for (int o = 16; o; o >>= 1) p += __shfl_xor_sync(0xffffffffu, p, o);
        if (lane == 0) hsm[r] = fmaxf(p + fc1b[r], 0.f);
    }
    __syncthreads();
    for (int c = t; c < 512; c += 256) {
        float s = fc2b[c];
#pragma unroll
        for (int r = 0; r < 32; r++) s += hsm[r] * fc2w[c * 32 + r];
        g_gate[b * 512 + c] = 1.f / (1.f + expf(-s));
    }
}

// ---------------- weight rounding (tf32 RNE) ------------------------------------
__global__ void k_roundw(const float* __restrict__ ipw, const float* __restrict__ opw,
                         const float* __restrict__ pw)
{
    int i = blockIdx.x * 256 + threadIdx.x;
    if (i < Gg * 256 * 128) g_ipw[i] = tf32r(ipw[i]);
    if (i < Gg * 128 * 128) g_opw[i] = tf32r(opw[i]);
    if (i < 512 * 512)      g_pw[i]  = tf32r(pw[i]);
}

// ---------------- GEMM 1: in_proj (fused SiLU on z half) ------------------------
__global__ void __launch_bounds__(256) k_gemm_in_mma()
{
    __shared__ float As[2 * STAGE_FLOATS], Bs[2 * STAGE_FLOATS];
    int g = blockIdx.z;
    int mBase = blockIdx.x * 128, nBase = blockIdx.y * 128;
    float acc[2][8][4] = {};
    mma_gemm<8>(g_xn + g * 128, Cch, g_ipw + (size_t)g * 256 * 128,
                mBase, nBase, acc, As, Bs);
    int lane = threadIdx.x & 31, wid = threadIdx.x >> 5;
    int gid = lane >> 2, tidx = lane & 3;
    int wm = (wid & 3) * 32, wn = (wid >> 2) * 64;
    bool dosilu = (nBase >= 128);
    float* Cp = g_xz + (size_t)g * Mrows * 256;
#pragma unroll
    for (int mt = 0; mt < 2; mt++)
#pragma unroll
    for (int half = 0; half < 2; half++) {
        int m = mBase + wm + mt * 16 + gid + half * 8;
        float* dst = Cp + (size_t)m * 256 + nBase + wn + 2 * tidx;
#pragma unroll
        for (int nt = 0; nt < 8; nt++) {
            float v0 = acc[mt][nt][half * 2], v1 = acc[mt][nt][half * 2 + 1];
            if (dosilu) { v0 = v0 / (1.f + expf(-v0)); v1 = v1 / (1.f + expf(-v1)); }
            float2 o = { v0, v1 };
            *(float2*)(dst + nt * 8) = o;
        }
    }
}

// ---------------- GEMM 2: out_proj ----------------------------------------------
__global__ void __launch_bounds__(256) k_gemm_out_mma()
{
    __shared__ float As[2 * STAGE_FLOATS], Bs[2 * STAGE_FLOATS];
    int g = blockIdx.z;
    int mBase = blockIdx.x * 128;
    float acc[2][8][4] = {};
    mma_gemm<8>(g_yz + (size_t)g * Mrows * 128, 128, g_opw + (size_t)g * 128 * 128,
                mBase, 0, acc, As, Bs);
    int lane = threadIdx.x & 31, wid = threadIdx.x >> 5;
    int gid = lane >> 2, tidx = lane & 3;
    int wm = (wid & 3) * 32, wn = (wid >> 2) * 64;
#pragma unroll
    for (int mt = 0; mt < 2; mt++)
#pragma unroll
    for (int half = 0; half < 2; half++) {
        int m = mBase + wm + mt * 16 + gid + half * 8;
        float* dst = g_ycat + (size_t)m * 512 + g * 128 + wn + 2 * tidx;
#pragma unroll
        for (int nt = 0; nt < 8; nt++) {
            float2 o = { acc[mt][nt][half * 2], acc[mt][nt][half * 2 + 1] };
            *(float2*)(dst + nt * 8) = o;
        }
    }
}

// ---------------- GEMM 3: final proj (transposed store + bias) -------------------
__global__ void __launch_bounds__(256) k_gemm_fin_mma(const float* __restrict__ pb,
                                                      float* __restrict__ out)
{
    __shared__ float As[2 * STAGE_FLOATS], Bs[2 * STAGE_FLOATS];
    int mBase = blockIdx.x * 128, nBase = blockIdx.y * 128;
    float acc[2][8][4] = {};
    mma_gemm<32>(g_xmn, 512, g_pw, mBase, nBase, acc, As, Bs);
    int lane = threadIdx.x & 31, wid = threadIdx.x >> 5;
    int gid = lane >> 2, tidx = lane & 3;
    int wm = (wid & 3) * 32, wn = (wid >> 2) * 64;
#pragma unroll
    for (int mt = 0; mt < 2; mt++)
#pragma unroll
    for (int half = 0; half < 2; half++) {
        int m = mBase + wm + mt * 16 + gid + half * 8;
        int b = m >> 12, l = m & 4095;
#pragma unroll
        for (int nt = 0; nt < 8; nt++) {
            int n = nBase + wn + nt * 8 + 2 * tidx;
            out[((size_t)(b * 512 + n)) * 4096 + l]     = acc[mt][nt][half * 2]     + __ldg(pb + n);
            out[((size_t)(b * 512 + n + 1)) * 4096 + l] = acc[mt][nt][half * 2 + 1] + __ldg(pb + n + 1);
        }
    }
}

// ---------------- kernel 5: depthwise conv + silu + cross_scan -----------------
__global__ void __launch_bounds__(256) k_conv(const float* __restrict__ cw,
                                              const float* __restrict__ cb)
{
    __shared__ float sx[324 * 32];
    __shared__ float wsm[32 * 9];
    __shared__ float bsm[32];
    int tile = blockIdx.x, dt = blockIdx.y, gb = blockIdx.z;
    int g = gb >> 3, b = gb & 7;
    int h0 = (tile >> 2) * 16, w0 = (tile & 3) * 16;
    int dbase = dt * 32;
    int tid = threadIdx.x;
    const float* src = g_xz + ((size_t)g * Mrows + b * Ls) * 256;
    for (int idx = tid; idx < 324 * 32; idx += 256) {
        int pos = idx >> 5, dd = idx & 31;
        int h = h0 + pos / 18 - 1, w = w0 + pos % 18 - 1;
        float v = 0.f;
        if (h >= 0 && h < 64 && w >= 0 && w < 64)
            v = src[(size_t)(h * 64 + w) * 256 + dbase + dd];
        sx[idx] = v;
    }
    for (int i = tid; i < 288; i += 256)
        wsm[i] = cw[(size_t)(g * 128 + dbase + i / 9) * 9 + i % 9];
    if (tid < 32)  bsm[tid] = cb[g * 128 + dbase + tid];
    __syncthreads();
    int dd = tid & 31;
    float* dstbase = g_u + ((size_t)g * Mrows + b * Ls) * 128 + dbase + dd;
#pragma unroll 4
    for (int it = 0; it < 32; it++) {
        int pos = it * 8 + (tid >> 5);
        int ph = pos >> 4, pw = pos & 15;
        float acc = bsm[dd];
#pragma unroll
        for (int kh = 0; kh < 3; kh++)
#pragma unroll
            for (int kw = 0; kw < 3; kw++)
                acc += sx[((ph + kh) * 18 + pw + kw) * 32 + dd] * wsm[dd * 9 + kh * 3 + kw];
        acc = acc / (1.f + expf(-acc));
        int h = h0 + ph, w = w0 + pw;
        int lp;
        if (g == 0)      lp = h * 64 + w;
        else if (g == 1) lp = w * 64 + h;
        else if (g == 2) lp = 4095 - (h * 64 + w);
        else             lp = 4095 - (w * 64 + h);
        dstbase[(size_t)lp * 128] = acc;
    }
}

// ---------------- kernel 6: x_proj + dt_proj + dA/dBu/C + chunk scan summary ---
// One block covers one 64-element scan chunk (8 warps x 8 steps).
__global__ void __launch_bounds__(256) k_proj(const float* __restrict__ xpw,
                                              const float* __restrict__ dtw_g,
                                              const float* __restrict__ dtb_g,
                                              const float* __restrict__ alog)
{
    __shared__ float xp[10 * 128];
    __shared__ float dtwT[8 * 128];
    __shared__ float dtb[128];
    __shared__ float An[128];
    __shared__ float sP[8][128], sH[8][128];
    int tid = threadIdx.x, lane = tid & 31, warp = tid >> 5;
    int chunk0 = blockIdx.x * 8;
    int g = chunk0 >> 12;
    for (int i = tid; i < 1280; i += 256) xp[i] = xpw[(size_t)g * 1280 + i];
    for (int i = tid; i < 1024; i += 256) {
        int r = i >> 7, d = i & 127;
        dtwT[i] = dtw_g[(size_t)(g * 128 + d) * 8 + r];
    }
    if (tid < 128) { dtb[tid] = dtb_g[g * 128 + tid]; An[tid] = -expf(alog[g * 128 + tid]); }
    __syncthreads();
    int chunk = chunk0 + warp;
    int b = (chunk >> 9) & 7;
    int lp0 = (chunk & 511) * 8;
    size_t rowbase = (size_t)(g * 8 + b) * 4096 + lp0;
    float hseg[4] = {0.f, 0.f, 0.f, 0.f};
    float Pseg[4] = {1.f, 1.f, 1.f, 1.f};
    for (int it = 0; it < 8; it++) {
        size_t row = rowbase + it;
        float4 u4 = *(const float4*)(g_u + row * 128 + lane * 4);
        float xdbl[10];
#pragma unroll
        for (int c = 0; c < 10; c++) {
            const float* xc = xp + c * 128 + lane * 4;
            float p = u4.x * xc[0] + u4.y * xc[1] + u4.z * xc[2] + u4.w * xc[3];
#pragma unroll
            for (int o = 16; o; o >>= 1) p += __shfl_xor_sync(0xffffffffu, p, o);
            xdbl[c] = p;
        }
        float Bm = xdbl[8];
        float uarr[4] = { u4.x, u4.y, u4.z, u4.w };
        float dA4[4], db4[4];
#pragma unroll
        for (int j = 0; j < 4; j++) {
            int d = lane * 4 + j;
            float s = dtb[d];
#pragma unroll
            for (int r = 0; r < 8; r++) s += xdbl[r] * dtwT[r * 128 + d];
            float delta = (s > 20.f) ? s : log1pf(expf(s));
            dA4[j] = expf(delta * An[d]);
            db4[j] = delta * uarr[j] * Bm;
            hseg[j] = fmaf(dA4[j], hseg[j], db4[j]);
            Pseg[j] *= dA4[j];
        }
        *(float4*)(g_dA  + row * 128 + lane * 4) = *(float4*)dA4;
        *(float4*)(g_dbu + row * 128 + lane * 4) = *(float4*)db4;
        if (lane == 0) g_Cv[row] = xdbl[9];
    }
    // chunk summary: compose the 8 warp segments sequentially
#pragma unroll
    for (int j = 0; j < 4; j++) { sP[warp][lane * 4 + j] = Pseg[j]; sH[warp][lane * 4 + j] = hseg[j]; }
    __syncthreads();
    if (tid < 128) {
        int d = tid;
        float h = 0.f, P = 1.f;
#pragma unroll
        for (int w = 0; w < 8; w++) {
            h = fmaf(sP[w][d], h, sH[w][d]);
            P *= sP[w][d];
        }
        int gb = g * 8 + b;
        int ch = (chunk0 & 511) >> 3;
        size_t o = ((size_t)gb * 64 + ch) * 128 + d;
        g_P[o] = P; g_hc[o] = h;
    }
}

// ---------------- kernel 7: inter-chunk serial scan ------------------------------
__global__ void k_scanB()
{
    int gb = blockIdx.x, d = threadIdx.x;
    float h = 0.f;
    for (int ch = 0; ch < 64; ch++) {
        size_t o = ((size_t)gb * 64 + ch) * 128 + d;
        g_hin[o] = h;
        h = fmaf(g_P[o], h, g_hc[o]);
    }
}

// ---------------- kernel 8: scanC fused with cross_merge + LN(D) + *z -----------
__global__ void __launch_bounds__(128) k_scanC_merge(const float* __restrict__ Dsp,
                                                     const float* __restrict__ og_,
                                                     const float* __restrict__ ob_)
{
    __shared__ float sS[2][4], sQ[2][4];
    int chunk = blockIdx.x, gb = blockIdx.y, d = threadIdx.x;
    int g = gb >> 3;
    int lane = d & 31, warp = d >> 5;
    float Ds  = Dsp[g * 128 + d];
    float ogv = og_[g * 128 + d];
    float obv = ob_[g * 128 + d];
    size_t base = ((size_t)gb * 4096 + chunk * 64) * 128 + d;
    size_t crow = (size_t)gb * 4096 + chunk * 64;
    float h = g_hin[((size_t)gb * 64 + chunk) * 128 + d];
    for (int i = 0; i < 64; i++) {
        size_t idx = base + (size_t)i * 128;
        h = fmaf(g_dA[idx], h, g_dbu[idx]);
        float yv = h * g_Cv[crow + i] + Ds * g_u[idx];
        // block-wide LN over the 128 d's
        float s = yv, q = yv * yv;
#pragma unroll
        for (int o = 16; o; o >>= 1) {
            s += __shfl_xor_sync(0xffffffffu, s, o);
            q += __shfl_xor_sync(0xffffffffu, q, o);
        }
        int slot = i & 1;
        if (lane == 0) { sS[slot][warp] = s; sQ[slot][warp] = q; }
        __syncthreads();
        s = sS[slot][0] + sS[slot][1] + sS[slot][2] + sS[slot][3];
        q = sQ[slot][0] + sQ[slot][1] + sQ[slot][2] + sQ[slot][3];
        float mu = s * (1.f / 128.f);
        float rs = rsqrtf(q * (1.f / 128.f) - mu * mu + 1e-5f);
        // inverse cross_scan permutation: scan pos -> spatial pos
        int lp = chunk * 64 + i;
        int l;
        if (g == 0)      l = lp;
        else if (g == 1) l = (lp & 63) * 64 + (lp >> 6);
        else if (g == 2) l = 4095 - lp;
        else { int t2 = 4095 - lp; l = (t2 & 63) * 64 + (t2 >> 6); }
        size_t drow = (size_t)gb * 4096 + l;
        float z = g_xz[drow * 256 + 128 + d];
        g_yz[drow * 128 + d] = tf32r(((yv - mu) * rs * ogv + obv) * z);
    }
}

// ---------------- kernel 12: mix + gate + LN(C) ---------------------------------
__global__ void __launch_bounds__(128) k_premix(const float* __restrict__ lg,
                                                const float* __restrict__ lb,
                                                const float* __restrict__ skip)
{
    int row = blockIdx.x, b = row >> 12, tid = threadIdx.x;
    float sk = skip[0];
    float4 yc = *(const float4*)(g_ycat + (size_t)row * 512 + tid * 4);
    float4 xn = *(const float4*)(g_xn   + (size_t)row * 512 + tid * 4);
    float4 gt = *(const float4*)(g_gate + (size_t)b   * 512 + tid * 4);
    float v[4] = { yc.x * sk * xn.x * gt.x, yc.y * sk * xn.y * gt.y,
                   yc.z * sk * xn.z * gt.z, yc.w * sk * xn.w * gt.w };
    float s  = v[0] + v[1] + v[2] + v[3];
    float s2 = v[0] * v[0] + v[1] * v[1] + v[2] * v[2] + v[3] * v[3];
#pragma unroll
    for (int o = 16; o; o >>= 1) {
        s  += __shfl_xor_sync(0xffffffffu, s, o);
        s2 += __shfl_xor_sync(0xffffffffu, s2, o);
    }
    __shared__ float rs_[4], rq_[4];
    int warp = tid >> 5, lane = tid & 31;
    if (lane == 0) { rs_[warp] = s; rq_[warp] = s2; }
    __syncthreads();
    s  = rs_[0] + rs_[1] + rs_[2] + rs_[3];
    s2 = rq_[0] + rq_[1] + rq_[2] + rq_[3];
    float mu = s * (1.f / 512.f);
    float rstd = rsqrtf(s2 * (1.f / 512.f) - mu * mu + 1e-5f);
    float o4[4];
#pragma unroll
    for (int j = 0; j < 4; j++) {
        int c = tid * 4 + j;
        o4[j] = tf32r((v[j] - mu) * rstd * lg[c] + lb[c]);
    }
    *(float4*)(g_xmn + (size_t)row * 512 + tid * 4) = *(float4*)o4;
}

// ---------------- launch ---------------------------------------------------------
extern "C" void kernel_launch(void* const* d_in, const int* in_sizes, int n_in,
                              void* d_out, int out_size)
{
    const float* x    = (const float*)d_in[0];
    const float* ln_g = (const float*)d_in[1];
    const float* ln_b = (const float*)d_in[2];
    const float* fc1w = (const float*)d_in[3];
    const float* fc1b = (const float*)d_in[4];
    const float* fc2w = (const float*)d_in[5];
    const float* fc2b = (const float*)d_in[6];
    const float* ipw  = (const float*)d_in[7];
    const float* cw   = (const float*)d_in[8];
    const float* cb   = (const float*)d_in[9];
    const float* xpw  = (const float*)d_in[10];
    const float* dtw  = (const float*)d_in[11];
    const float* dtb  = (const float*)d_in[12];
    const float* alog = (const float*)d_in[13];
    const float* dsp  = (const float*)d_in[14];
    const float* ong  = (const float*)d_in[15];
    const float* onb  = (const float*)d_in[16];
    const float* opw  = (const float*)d_in[17];
    const float* pw   = (const float*)d_in[18];
    const float* pb   = (const float*)d_in[19];
    const float* skip = (const float*)d_in[20];
    float* out = (float*)d_out;

    k_ln1         <<<dim3(32, 8),     128>>>(x, ln_g, ln_b);
    k_roundw      <<<1024,            256>>>(ipw, opw, pw);
    k_zsum        <<<dim3(32, 8),     512>>>();
    k_gate        <<<8,               256>>>(fc1w, fc1b, fc2w, fc2b);
    k_gemm_in_mma <<<dim3(256, 2, 4), 256>>>();
    k_conv        <<<dim3(16, 4, 32), 256>>>(cw, cb);
    k_proj        <<<2048,            256>>>(xpw, dtw, dtb, alog);
    k_scanB       <<<32,              128>>>();
    k_scanC_merge <<<dim3(64, 32),    128>>>(dsp, ong, onb);
    k_gemm_out_mma<<<dim3(256, 1, 4), 256>>>();
    k_premix      <<<32768,           128>>>(ln_g, ln_b, skip);
    k_gemm_fin_mma<<<dim3(256, 4),    256>>>(pb, out);
}

// round 14
// speedup vs baseline: 1.0037x; 1.0037x over previous
#include <cuda_runtime.h>
#include <math.h>
#include <stdint.h>

// Problem constants
#define Bsz 8
#define Cch 512
#define Ls 4096
#define Gg 4
#define Dd 128
#define Mrows 32768   // B*L

// ---------------- scratch (device globals; no cudaMalloc allowed) -------------
__device__ float g_xn  [(size_t)Bsz*Ls*Cch];
__device__ float g_zp  [32*Bsz*Cch];
__device__ float g_gate[Bsz*Cch];
__device__ float g_xz  [(size_t)Gg*Mrows*256];
__device__ float g_u   [(size_t)Gg*Mrows*Dd];
__device__ float g_dA  [(size_t)Gg*Mrows*Dd];
__device__ float g_dbu [(size_t)Gg*Mrows*Dd];
__device__ float g_Cv  [Gg*Mrows];
__device__ float g_P   [Gg*Bsz*64*Dd];
__device__ float g_hc  [Gg*Bsz*64*Dd];
__device__ float g_hin [Gg*Bsz*64*Dd];
__device__ float g_yz  [(size_t)Gg*Mrows*Dd];
__device__ float g_ycat[(size_t)Mrows*Cch];
__device__ float g_xmn [(size_t)Mrows*Cch];
// tf32-rounded weight copies
__device__ float g_ipw [Gg*256*128];
__device__ float g_opw [Gg*128*128];
__device__ float g_pw  [512*512];

// ---------------- helpers -------------------------------------------------------
__device__ __forceinline__ float tf32r(float x) {
    uint32_t u;
    asm("cvt.rna.tf32.f32 %0, %1;" : "=r"(u) : "f"(x));
    return __uint_as_float(u);
}
__device__ __forceinline__ uint32_t sm_u32(const void* p) {
    return (uint32_t)__cvta_generic_to_shared(p);
}
__device__ __forceinline__ void cpa16(uint32_t dst, const float* src) {
    asm volatile("cp.async.cg.shared.global [%0], [%1], 16;" :: "r"(dst), "l"(src));
}
__device__ __forceinline__ void cpa_commit() { asm volatile("cp.async.commit_group;"); }
template<int N> __device__ __forceinline__ void cpa_wait() {
    asm volatile("cp.async.wait_group %0;" :: "n"(N));
}
__device__ __forceinline__ void mma_tf32_16n8k8(float* c, const uint32_t* a, const uint32_t* b) {
    asm volatile(
        "mma.sync.aligned.m16n8k8.row.col.f32.tf32.tf32.f32 "
        "{%0,%1,%2,%3}, {%4,%5,%6,%7}, {%8,%9}, {%0,%1,%2,%3};"
        : "+f"(c[0]), "+f"(c[1]), "+f"(c[2]), "+f"(c[3])
        : "r"(a[0]), "r"(a[1]), "r"(a[2]), "r"(a[3]), "r"(b[0]), "r"(b[1]));
}

// SMEM stage: 128 rows x 16 cols, pitch 20 floats (conflict-free fragments)
#define SPITCH 20
#define STAGE_FLOATS (128 * SPITCH)           // 2560 floats per matrix stage
#define STAGE_PAIR   (2 * STAGE_FLOATS)       // A+B per stage
#define GEMM_SMEM3   (3 * STAGE_PAIR * 4)     // 61440 bytes

// 128-thread stage loader: 128 rows x 16 cols
__device__ __forceinline__ void stage_load128(const float* __restrict__ g, int ld,
                                              int r0, int k0, float* sbuf, int tid)
{
#pragma unroll
    for (int i = 0; i < 4; i++) {
        int s = tid + (i << 7);          // 0..511
        int r = s >> 2, seg = s & 3;
        cpa16(sm_u32(sbuf + r * SPITCH + seg * 4),
              g + (size_t)(r0 + r) * ld + k0 + seg * 4);
    }
}

// ---------------- tf32 mma.sync 128x128xK core (4 warps, 64x64 warp tile) -------
// 3-stage cp.async pipeline, one barrier per stage. acc[mt 0..3][nt 0..7][4].
template<int S>   // S = K/16 stages
__device__ __forceinline__ void mma_gemm(const float* __restrict__ Ag, int lda,
                                         const float* __restrict__ Bg,
                                         int mBase, int nBase,
                                         float acc[4][8][4])
{
    extern __shared__ float dsm[];
    const int KTOT = 16 * S;
    int tid = threadIdx.x, wid = tid >> 5, lane = tid & 31;
    int gid = lane >> 2, tidx = lane & 3;
    int wm = (wid & 1) * 64, wn = (wid >> 1) * 64;

    // prologue: stages 0 and 1
    stage_load128(Ag, lda, mBase, 0, dsm, tid);
    stage_load128(Bg, KTOT, nBase, 0, dsm + STAGE_FLOATS, tid);
    cpa_commit();
    stage_load128(Ag, lda, mBase, 16, dsm + STAGE_PAIR, tid);
    stage_load128(Bg, KTOT, nBase, 16, dsm + STAGE_PAIR + STAGE_FLOATS, tid);
    cpa_commit();

    int sslot = 0;
    for (int s = 0; s < S; s++) {
        if (s + 1 < S) cpa_wait<1>(); else cpa_wait<0>();
        __syncthreads();
        if (s + 2 < S) {
            int ns = sslot + 2; if (ns >= 3) ns -= 3;
            float* nb = dsm + ns * STAGE_PAIR;
            stage_load128(Ag, lda, mBase, (s + 2) * 16, nb, tid);
            stage_load128(Bg, KTOT, nBase, (s + 2) * 16, nb + STAGE_FLOATS, tid);
            cpa_commit();
        }
        const float* Ab = dsm + sslot * STAGE_PAIR;
        const float* Bb = Ab + STAGE_FLOATS;
#pragma unroll
        for (int kk = 0; kk < 16; kk += 8) {
            uint32_t afr[4][4];
#pragma unroll
            for (int mt = 0; mt < 4; mt++) {
                const float* ap = Ab + (wm + mt * 16 + gid) * SPITCH + kk + tidx;
                afr[mt][0] = __float_as_uint(ap[0]);
                afr[mt][1] = __float_as_uint(ap[8 * SPITCH]);
                afr[mt][2] = __float_as_uint(ap[4]);
                afr[mt][3] = __float_as_uint(ap[8 * SPITCH + 4]);
            }
#pragma unroll
            for (int nh = 0; nh < 2; nh++) {
                uint32_t bfr[4][2];
#pragma unroll
                for (int j = 0; j < 4; j++) {
                    const float* bp = Bb + (wn + (nh * 4 + j) * 8 + gid) * SPITCH + kk + tidx;
                    bfr[j][0] = __float_as_uint(bp[0]);
                    bfr[j][1] = __float_as_uint(bp[4]);
                }
#pragma unroll
                for (int mt = 0; mt < 4; mt++)
#pragma unroll
                    for (int j = 0; j < 4; j++)
                        mma_tf32_16n8k8(acc[mt][nh * 4 + j], afr[mt], bfr[j]);
            }
        }
        if (++sslot == 3) sslot = 0;
    }
}

// ---------------- kernel 1: layernorm over C ----------------------------------
__global__ void k_ln1(const float* __restrict__ x,
                      const float* __restrict__ lg, const float* __restrict__ lb)
{
    int b = blockIdx.y;
    int l = blockIdx.x * 128 + threadIdx.x;
    const float* xp = x + (size_t)b * Cch * Ls + l;
    float s = 0.f, s2 = 0.f;
#pragma unroll 8
    for (int c = 0; c < Cch; c++) { float v = xp[(size_t)c * Ls]; s += v; s2 += v * v; }
    float mu = s * (1.f / Cch);
    float rs = rsqrtf(s2 * (1.f / Cch) - mu * mu + 1e-5f);
    float* out = g_xn + ((size_t)b * Ls + l) * Cch;
#pragma unroll 4
    for (int c = 0; c < Cch; c += 4) {
        float4 o;
        o.x = tf32r((xp[(size_t)(c + 0) * Ls] - mu) * rs * lg[c + 0] + lb[c + 0]);
        o.y = tf32r((xp[(size_t)(c + 1) * Ls] - mu) * rs * lg[c + 1] + lb[c + 1]);
        o.z = tf32r((xp[(size_t)(c + 2) * Ls] - mu) * rs * lg[c + 2] + lb[c + 2]);
        o.w = tf32r((xp[(size_t)(c + 3) * Ls] - mu) * rs * lg[c + 3] + lb[c + 3]);
        *(float4*)(out + c) = o;
    }
}

// ---------------- kernel 2: partial column sums -------------------------------
__global__ void k_zsum()
{
    int b = blockIdx.y, k = blockIdx.x, c = threadIdx.x;
    const float* p = g_xn + ((size_t)b * Ls + k * 128) * Cch + c;
    float s = 0.f;
#pragma unroll 8
    for (int i = 0; i < 128; i++) s += p[(size_t)i * Cch];
    g_zp[(k * Bsz + b) * Cch + c] = s;
}

// ---------------- kernel 3: gate MLP — parallel (one block per batch) ----------
__global__ void __launch_bounds__(256) k_gate(const float* __restrict__ fc1w,
                                              const float* __restrict__ fc1b,
                                              const float* __restrict__ fc2w,
                                              const float* __restrict__ fc2b)
{
    __shared__ float zsm[512];
    __shared__ float hsm[32];
    int t = threadIdx.x, b = blockIdx.x;
    int warp = t >> 5, lane = t & 31;
    for (int c = t; c < 512; c += 256) {
        float s = 0.f;
#pragma unroll
        for (int k = 0; k < 32; k++) s += g_zp[(k * Bsz + b) * 512 + c];
        zsm[c] = s * (1.f / Ls);
    }
    __syncthreads();
    for (int r = warp; r < 32; r += 8) {
        float p = 0.f;
#pragma unroll 4
        for (int i = lane; i < 512; i += 32) p += zsm[i] * fc1w[r * 512 + i];
#pragma unroll
        for (int o = 16; o; o >>= 1) p += __shfl_xor_sync(0xffffffffu, p, o);
        if (lane == 0) hsm[r] = fmaxf(p + fc1b[r], 0.f);
    }
    __syncthreads();
    for (int c = t; c < 512; c += 256) {
        float s = fc2b[c];
#pragma unroll
        for (int r = 0; r < 32; r++) s += hsm[r] * fc2w[c * 32 + r];
        g_gate[b * 512 + c] = 1.f / (1.f + expf(-s));
    }
}

// ---------------- weight rounding (tf32 RNE) ------------------------------------
__global__ void k_roundw(const float* __restrict__ ipw, const float* __restrict__ opw,
                         const float* __restrict__ pw)
{
    int i = blockIdx.x * 256 + threadIdx.x;
    if (i < Gg * 256 * 128) g_ipw[i] = tf32r(ipw[i]);
    if (i < Gg * 128 * 128) g_opw[i] = tf32r(opw[i]);
    if (i < 512 * 512)      g_pw[i]  = tf32r(pw[i]);
}

// ---------------- GEMM 1: in_proj (fused SiLU on z half) ------------------------
__global__ void __launch_bounds__(128) k_gemm_in_mma()
{
    int g = blockIdx.z;
    int mBase = blockIdx.x * 128, nBase = blockIdx.y * 128;
    float acc[4][8][4] = {};
    mma_gemm<8>(g_xn + g * 128, Cch, g_ipw + (size_t)g * 256 * 128,
                mBase, nBase, acc);
    int lane = threadIdx.x & 31, wid = threadIdx.x >> 5;
    int gid = lane >> 2, tidx = lane & 3;
    int wm = (wid & 1) * 64, wn = (wid >> 1) * 64;
    bool dosilu = (nBase >= 128);
    float* Cp = g_xz + (size_t)g * Mrows * 256;
#pragma unroll
    for (int mt = 0; mt < 4; mt++)
#pragma unroll
    for (int half = 0; half < 2; half++) {
        int m = mBase + wm + mt * 16 + gid + half * 8;
        float* dst = Cp + (size_t)m * 256 + nBase + wn + 2 * tidx;
#pragma unroll
        for (int nt = 0; nt < 8; nt++) {
            float v0 = acc[mt][nt][half * 2], v1 = acc[mt][nt][half * 2 + 1];
            if (dosilu) { v0 = v0 / (1.f + expf(-v0)); v1 = v1 / (1.f + expf(-v1)); }
            float2 o = { v0, v1 };
            *(float2*)(dst + nt * 8) = o;
        }
    }
}

// ---------------- GEMM 2: out_proj ----------------------------------------------
__global__ void __launch_bounds__(128) k_gemm_out_mma()
{
    int g = blockIdx.z;
    int mBase = blockIdx.x * 128;
    float acc[4][8][4] = {};
    mma_gemm<8>(g_yz + (size_t)g * Mrows * 128, 128, g_opw + (size_t)g * 128 * 128,
                mBase, 0, acc);
    int lane = threadIdx.x & 31, wid = threadIdx.x >> 5;
    int gid = lane >> 2, tidx = lane & 3;
    int wm = (wid & 1) * 64, wn = (wid >> 1) * 64;
#pragma unroll
    for (int mt = 0; mt < 4; mt++)
#pragma unroll
    for (int half = 0; half < 2; half++) {
        int m = mBase + wm + mt * 16 + gid + half * 8;
        float* dst = g_ycat + (size_t)m * 512 + g * 128 + wn + 2 * tidx;
#pragma unroll
        for (int nt = 0; nt < 8; nt++) {
            float2 o = { acc[mt][nt][half * 2], acc[mt][nt][half * 2 + 1] };
            *(float2*)(dst + nt * 8) = o;
        }
    }
}

// ---------------- GEMM 3: final proj (transposed store + bias) -------------------
__global__ void __launch_bounds__(128) k_gemm_fin_mma(const float* __restrict__ pb,
                                                      float* __restrict__ out)
{
    int mBase = blockIdx.x * 128, nBase = blockIdx.y * 128;
    float acc[4][8][4] = {};
    mma_gemm<32>(g_xmn, 512, g_pw, mBase, nBase, acc);
    int lane = threadIdx.x & 31, wid = threadIdx.x >> 5;
    int gid = lane >> 2, tidx = lane & 3;
    int wm = (wid & 1) * 64, wn = (wid >> 1) * 64;
#pragma unroll
    for (int mt = 0; mt < 4; mt++)
#pragma unroll
    for (int half = 0; half < 2; half++) {
        int m = mBase + wm + mt * 16 + gid + half * 8;
        int b = m >> 12, l = m & 4095;
#pragma unroll
        for (int nt = 0; nt < 8; nt++) {
            int n = nBase + wn + nt * 8 + 2 * tidx;
            out[((size_t)(b * 512 + n)) * 4096 + l]     = acc[mt][nt][half * 2]     + __ldg(pb + n);
            out[((size_t)(b * 512 + n + 1)) * 4096 + l] = acc[mt][nt][half * 2 + 1] + __ldg(pb + n + 1);
        }
    }
}

// ---------------- kernel 5: depthwise conv + silu + cross_scan -----------------
__global__ void __launch_bounds__(256) k_conv(const float* __restrict__ cw,
                                              const float* __restrict__ cb)
{
    __shared__ float sx[324 * 32];
    __shared__ float wsm[32 * 9];
    __shared__ float bsm[32];
    int tile = blockIdx.x, dt = blockIdx.y, gb = blockIdx.z;
    int g = gb >> 3, b = gb & 7;
    int h0 = (tile >> 2) * 16, w0 = (tile & 3) * 16;
    int dbase = dt * 32;
    int tid = threadIdx.x;
    const float* src = g_xz + ((size_t)g * Mrows + b * Ls) * 256;
    for (int idx = tid; idx < 324 * 32; idx += 256) {
        int pos = idx >> 5, dd = idx & 31;
        int h = h0 + pos / 18 - 1, w = w0 + pos % 18 - 1;
        float v = 0.f;
        if (h >= 0 && h < 64 && w >= 0 && w < 64)
            v = src[(size_t)(h * 64 + w) * 256 + dbase + dd];
        sx[idx] = v;
    }
    for (int i = tid; i < 288; i += 256)
        wsm[i] = cw[(size_t)(g * 128 + dbase + i / 9) * 9 + i % 9];
    if (tid < 32)  bsm[tid] = cb[g * 128 + dbase + tid];
    __syncthreads();
    int dd = tid & 31;
    float* dstbase = g_u + ((size_t)g * Mrows + b * Ls) * 128 + dbase + dd;
#pragma unroll 4
    for (int it = 0; it < 32; it++) {
        int pos = it * 8 + (tid >> 5);
        int ph = pos >> 4, pw = pos & 15;
        float acc = bsm[dd];
#pragma unroll
        for (int kh = 0; kh < 3; kh++)
#pragma unroll
            for (int kw = 0; kw < 3; kw++)
                acc += sx[((ph + kh) * 18 + pw + kw) * 32 + dd] * wsm[dd * 9 + kh * 3 + kw];
        acc = acc / (1.f + expf(-acc));
        int h = h0 + ph, w = w0 + pw;
        int lp;
        if (g == 0)      lp = h * 64 + w;
        else if (g == 1) lp = w * 64 + h;
        else if (g == 2) lp = 4095 - (h * 64 + w);
        else             lp = 4095 - (w * 64 + h);
        dstbase[(size_t)lp * 128] = acc;
    }
}

// ---------------- kernel 6: x_proj + dt_proj + dA/dBu/C + chunk scan summary ---
__global__ void __launch_bounds__(256) k_proj(const float* __restrict__ xpw,
                                              const float* __restrict__ dtw_g,
                                              const float* __restrict__ dtb_g,
                                              const float* __restrict__ alog)
{
    __shared__ float xp[10 * 128];
    __shared__ float dtwT[8 * 128];
    __shared__ float dtb[128];
    __shared__ float An[128];
    __shared__ float sP[8][128], sH[8][128];
    int tid = threadIdx.x, lane = tid & 31, warp = tid >> 5;
    int chunk0 = blockIdx.x * 8;
    int g = chunk0 >> 12;
    for (int i = tid; i < 1280; i += 256) xp[i] = xpw[(size_t)g * 1280 + i];
    for (int i = tid; i < 1024; i += 256) {
        int r = i >> 7, d = i & 127;
        dtwT[i] = dtw_g[(size_t)(g * 128 + d) * 8 + r];
    }
    if (tid < 128) { dtb[tid] = dtb_g[g * 128 + tid]; An[tid] = -expf(alog[g * 128 + tid]); }
    __syncthreads();
    int chunk = chunk0 + warp;
    int b = (chunk >> 9) & 7;
    int lp0 = (chunk & 511) * 8;
    size_t rowbase = (size_t)(g * 8 + b) * 4096 + lp0;
    float hseg[4] = {0.f, 0.f, 0.f, 0.f};
    float Pseg[4] = {1.f, 1.f, 1.f, 1.f};
    for (int it = 0; it < 8; it++) {
        size_t row = rowbase + it;
        float4 u4 = *(const float4*)(g_u + row * 128 + lane * 4);
        float xdbl[10];
#pragma unroll
        for (int c = 0; c < 10; c++) {
            const float* xc = xp + c * 128 + lane * 4;
            float p = u4.x * xc[0] + u4.y * xc[1] + u4.z * xc[2] + u4.w * xc[3];
#pragma unroll
            for (int o = 16; o; o >>= 1) p += __shfl_xor_sync(0xffffffffu, p, o);
            xdbl[c] = p;
        }
        float Bm = xdbl[8];
        float uarr[4] = { u4.x, u4.y, u4.z, u4.w };
        float dA4[4], db4[4];
#pragma unroll
        for (int j = 0; j < 4; j++) {
            int d = lane * 4 + j;
            float s = dtb[d];
#pragma unroll
            for (int r = 0; r < 8; r++) s += xdbl[r] * dtwT[r * 128 + d];
            float delta = (s > 20.f) ? s : log1pf(expf(s));
            dA4[j] = expf(delta * An[d]);
            db4[j] = delta * uarr[j] * Bm;
            hseg[j] = fmaf(dA4[j], hseg[j], db4[j]);
            Pseg[j] *= dA4[j];
        }
        *(float4*)(g_dA  + row * 128 + lane * 4) = *(float4*)dA4;
        *(float4*)(g_dbu + row * 128 + lane * 4) = *(float4*)db4;
        if (lane == 0) g_Cv[row] = xdbl[9];
    }
#pragma unroll
    for (int j = 0; j < 4; j++) { sP[warp][lane * 4 + j] = Pseg[j]; sH[warp][lane * 4 + j] = hseg[j]; }
    __syncthreads();
    if (tid < 128) {
        int d = tid;
        float h = 0.f, P = 1.f;
#pragma unroll
        for (int w = 0; w < 8; w++) {
            h = fmaf(sP[w][d], h, sH[w][d]);
            P *= sP[w][d];
        }
        int gb = g * 8 + b;
        int ch = (chunk0 & 511) >> 3;
        size_t o = ((size_t)gb * 64 + ch) * 128 + d;
        g_P[o] = P; g_hc[o] = h;
    }
}

// ---------------- kernel 7: inter-chunk serial scan ------------------------------
__global__ void k_scanB()
{
    int gb = blockIdx.x, d = threadIdx.x;
    float h = 0.f;
    for (int ch = 0; ch < 64; ch++) {
        size_t o = ((size_t)gb * 64 + ch) * 128 + d;
        g_hin[o] = h;
        h = fmaf(g_P[o], h, g_hc[o]);
    }
}

// ---------------- kernel 8: scanC fused with cross_merge + LN(D) + *z -----------
__global__ void __launch_bounds__(128) k_scanC_merge(const float* __restrict__ Dsp,
                                                     const float* __restrict__ og_,
                                                     const float* __restrict__ ob_)
{
    __shared__ float sS[2][4], sQ[2][4];
    int chunk = blockIdx.x, gb = blockIdx.y, d = threadIdx.x;
    int g = gb >> 3;
    int lane = d & 31, warp = d >> 5;
    float Ds  = Dsp[g * 128 + d];
    float ogv = og_[g * 128 + d];
    float obv = ob_[g * 128 + d];
    size_t base = ((size_t)gb * 4096 + chunk * 64) * 128 + d;
    size_t crow = (size_t)gb * 4096 + chunk * 64;
    float h = g_hin[((size_t)gb * 64 + chunk) * 128 + d];
    for (int i = 0; i < 64; i++) {
        size_t idx = base + (size_t)i * 128;
        h = fmaf(g_dA[idx], h, g_dbu[idx]);
        float yv = h * g_Cv[crow + i] + Ds * g_u[idx];
        float s = yv, q = yv * yv;
#pragma unroll
        for (int o = 16; o; o >>= 1) {
            s += __shfl_xor_sync(0xffffffffu, s, o);
            q += __shfl_xor_sync(0xffffffffu, q, o);
        }
        int slot = i & 1;
        if (lane == 0) { sS[slot][warp] = s; sQ[slot][warp] = q; }
        __syncthreads();
        s = sS[slot][0] + sS[slot][1] + sS[slot][2] + sS[slot][3];
        q = sQ[slot][0] + sQ[slot][1] + sQ[slot][2] + sQ[slot][3];
        float mu = s * (1.f / 128.f);
        float rs = rsqrtf(q * (1.f / 128.f) - mu * mu + 1e-5f);
        int lp = chunk * 64 + i;
        int l;
        if (g == 0)      l = lp;
        else if (g == 1) l = (lp & 63) * 64 + (lp >> 6);
        else if (g == 2) l = 4095 - lp;
        else { int t2 = 4095 - lp; l = (t2 & 63) * 64 + (t2 >> 6); }
        size_t drow = (size_t)gb * 4096 + l;
        float z = g_xz[drow * 256 + 128 + d];
        g_yz[drow * 128 + d] = tf32r(((yv - mu) * rs * ogv + obv) * z);
    }
}

// ---------------- kernel 12: mix + gate + LN(C) ---------------------------------
__global__ void __launch_bounds__(128) k_premix(const float* __restrict__ lg,
                                                const float* __restrict__ lb,
                                                const float* __restrict__ skip)
{
    int row = blockIdx.x, b = row >> 12, tid = threadIdx.x;
    float sk = skip[0];
    float4 yc = *(const float4*)(g_ycat + (size_t)row * 512 + tid * 4);
    float4 xn = *(const float4*)(g_xn   + (size_t)row * 512 + tid * 4);
    float4 gt = *(const float4*)(g_gate + (size_t)b   * 512 + tid * 4);
    float v[4] = { yc.x * sk * xn.x * gt.x, yc.y * sk * xn.y * gt.y,
                   yc.z * sk * xn.z * gt.z, yc.w * sk * xn.w * gt.w };
    float s  = v[0] + v[1] + v[2] + v[3];
    float s2 = v[0] * v[0] + v[1] * v[1] + v[2] * v[2] + v[3] * v[3];
#pragma unroll
    for (int o = 16; o; o >>= 1) {
        s  += __shfl_xor_sync(0xffffffffu, s, o);
        s2 += __shfl_xor_sync(0xffffffffu, s2, o);
    }
    __shared__ float rs_[4], rq_[4];
    int warp = tid >> 5, lane = tid & 31;
    if (lane == 0) { rs_[warp] = s; rq_[warp] = s2; }
    __syncthreads();
    s  = rs_[0] + rs_[1] + rs_[2] + rs_[3];
    s2 = rq_[0] + rq_[1] + rq_[2] + rq_[3];
    float mu = s * (1.f / 512.f);
    float rstd = rsqrtf(s2 * (1.f / 512.f) - mu * mu + 1e-5f);
    float o4[4];
#pragma unroll
    for (int j = 0; j < 4; j++) {
        int c = tid * 4 + j;
        o4[j] = tf32r((v[j] - mu) * rstd * lg[c] + lb[c]);
    }
    *(float4*)(g_xmn + (size_t)row * 512 + tid * 4) = *(float4*)o4;
}

// ---------------- launch ---------------------------------------------------------
extern "C" void kernel_launch(void* const* d_in, const int* in_sizes, int n_in,
                              void* d_out, int out_size)
{
    const float* x    = (const float*)d_in[0];
    const float* ln_g = (const float*)d_in[1];
    const float* ln_b = (const float*)d_in[2];
    const float* fc1w = (const float*)d_in[3];
    const float* fc1b = (const float*)d_in[4];
    const float* fc2w = (const float*)d_in[5];
    const float* fc2b = (const float*)d_in[6];
    const float* ipw  = (const float*)d_in[7];
    const float* cw   = (const float*)d_in[8];
    const float* cb   = (const float*)d_in[9];
    const float* xpw  = (const float*)d_in[10];
    const float* dtw  = (const float*)d_in[11];
    const float* dtb  = (const float*)d_in[12];
    const float* alog = (const float*)d_in[13];
    const float* dsp  = (const float*)d_in[14];
    const float* ong  = (const float*)d_in[15];
    const float* onb  = (const float*)d_in[16];
    const float* opw  = (const float*)d_in[17];
    const float* pw   = (const float*)d_in[18];
    const float* pb   = (const float*)d_in[19];
    const float* skip = (const float*)d_in[20];
    float* out = (float*)d_out;

    cudaFuncSetAttribute(k_gemm_in_mma,  cudaFuncAttributeMaxDynamicSharedMemorySize, GEMM_SMEM3);
    cudaFuncSetAttribute(k_gemm_out_mma, cudaFuncAttributeMaxDynamicSharedMemorySize, GEMM_SMEM3);
    cudaFuncSetAttribute(k_gemm_fin_mma, cudaFuncAttributeMaxDynamicSharedMemorySize, GEMM_SMEM3);

    // (gemm_in placed 4th so the profiler's captured launch is the GEMM core)
    k_ln1         <<<dim3(32, 8),     128>>>(x, ln_g, ln_b);
    k_roundw      <<<1024,            256>>>(ipw, opw, pw);
    k_zsum        <<<dim3(32, 8),     512>>>();
    k_gemm_in_mma <<<dim3(256, 2, 4), 128, GEMM_SMEM3>>>();
    k_gate        <<<8,               256>>>(fc1w, fc1b, fc2w, fc2b);
    k_conv        <<<dim3(16, 4, 32), 256>>>(cw, cb);
    k_proj        <<<2048,            256>>>(xpw, dtw, dtb, alog);
    k_scanB       <<<32,              128>>>();
    k_scanC_merge <<<dim3(64, 32),    128>>>(dsp, ong, onb);
    k_gemm_out_mma<<<dim3(256, 1, 4), 128, GEMM_SMEM3>>>();
    k_premix      <<<32768,           128>>>(ln_g, ln_b, skip);
    k_gemm_fin_mma<<<dim3(256, 4),    128, GEMM_SMEM3>>>(pb, out);
}

// round 15
// speedup vs baseline: 1.1841x; 1.1797x over previous
#include <cuda_runtime.h>
#include <cuda_fp16.h>
#include <math.h>
#include <stdint.h>

// Problem constants
#define Bsz 8
#define Cch 512
#define Ls 4096
#define Gg 4
#define Dd 128
#define Mrows 32768   // B*L

// ---------------- scratch (device globals; no cudaMalloc allowed) -------------
__device__ __half g_hxn [(size_t)Bsz*Ls*Cch];      // LN1 output (half)
__device__ float  g_zp  [32*Bsz*Cch];
__device__ float  g_gate[Bsz*Cch];
__device__ float  g_xz  [(size_t)Gg*Mrows*256];
__device__ float  g_u   [(size_t)Gg*Mrows*Dd];
__device__ float  g_dA  [(size_t)Gg*Mrows*Dd];
__device__ float  g_dbu [(size_t)Gg*Mrows*Dd];
__device__ float  g_Cv  [Gg*Mrows];
__device__ float  g_P   [Gg*Bsz*64*Dd];
__device__ float  g_hc  [Gg*Bsz*64*Dd];
__device__ float  g_hin [Gg*Bsz*64*Dd];
__device__ __half g_hyz [(size_t)Gg*Mrows*Dd];     // merged LN*z (half)
__device__ float  g_ycat[(size_t)Mrows*Cch];
__device__ __half g_hxmn[(size_t)Mrows*Cch];       // premix output (half)
// fp16-rounded weight copies
__device__ __half g_ipw [Gg*256*128];
__device__ __half g_opw [Gg*128*128];
__device__ __half g_pw  [512*512];

// ---------------- helpers -------------------------------------------------------
__device__ __forceinline__ uint32_t sm_u32(const void* p) {
    return (uint32_t)__cvta_generic_to_shared(p);
}
__device__ __forceinline__ void cpa16(uint32_t dst, const void* src) {
    asm volatile("cp.async.cg.shared.global [%0], [%1], 16;" :: "r"(dst), "l"(src));
}
__device__ __forceinline__ void cpa_commit() { asm volatile("cp.async.commit_group;"); }
template<int N> __device__ __forceinline__ void cpa_wait() {
    asm volatile("cp.async.wait_group %0;" :: "n"(N));
}
__device__ __forceinline__ void mma_f16_16n8k16(float* c, const uint32_t* a, const uint32_t* b) {
    asm volatile(
        "mma.sync.aligned.m16n8k16.row.col.f32.f16.f16.f32 "
        "{%0,%1,%2,%3}, {%4,%5,%6,%7}, {%8,%9}, {%0,%1,%2,%3};"
        : "+f"(c[0]), "+f"(c[1]), "+f"(c[2]), "+f"(c[3])
        : "r"(a[0]), "r"(a[1]), "r"(a[2]), "r"(a[3]), "r"(b[0]), "r"(b[1]));
}

// SMEM stage: 128 rows x 32 halves, pitch 40 halves (20 words -> conflict-free)
#define SPH 40
#define STAGE_H (128 * SPH)            // halves per matrix stage
#define SPAIR_H (2 * STAGE_H)          // A+B per stage (halves)
#define GEMM_SMEM3 (3 * SPAIR_H * 2)   // 61440 bytes

// 128-thread stage loader: 128 rows x 32 halves (64B/row = 4 x 16B)
__device__ __forceinline__ void stage_load_h(const __half* __restrict__ g, int ld,
                                             int r0, int k0, __half* sbuf, int tid)
{
#pragma unroll
    for (int i = 0; i < 4; i++) {
        int s = tid + (i << 7);
        int r = s >> 2, seg = s & 3;
        cpa16(sm_u32(sbuf + r * SPH + seg * 8),
              g + (size_t)(r0 + r) * ld + k0 + seg * 8);
    }
}

// ---------------- fp16 mma.sync 128x128xK core (4 warps, 64x64 warp tile) -------
// 3-stage cp.async pipeline, one barrier per stage. K=32 per stage.
template<int S>   // S = K/32 stages
__device__ __forceinline__ void mma_gemm_h(const __half* __restrict__ Ag, int lda,
                                           const __half* __restrict__ Bg,
                                           int mBase, int nBase,
                                           float acc[4][8][4])
{
    extern __shared__ __align__(16) char smraw[];
    __half* hsm = (__half*)smraw;
    const int KTOT = 32 * S;
    int tid = threadIdx.x, wid = tid >> 5, lane = tid & 31;
    int gid = lane >> 2, tidx = lane & 3;
    int wm = (wid & 1) * 64, wn = (wid >> 1) * 64;

    stage_load_h(Ag, lda, mBase, 0, hsm, tid);
    stage_load_h(Bg, KTOT, nBase, 0, hsm + STAGE_H, tid);
    cpa_commit();
    if (S > 1) {
        stage_load_h(Ag, lda, mBase, 32, hsm + SPAIR_H, tid);
        stage_load_h(Bg, KTOT, nBase, 32, hsm + SPAIR_H + STAGE_H, tid);
    }
    cpa_commit();

    int sslot = 0;
    for (int s = 0; s < S; s++) {
        if (s + 1 < S) cpa_wait<1>(); else cpa_wait<0>();
        __syncthreads();
        if (s + 2 < S) {
            int ns = sslot + 2; if (ns >= 3) ns -= 3;
            __half* nb = hsm + ns * SPAIR_H;
            stage_load_h(Ag, lda, mBase, (s + 2) * 32, nb, tid);
            stage_load_h(Bg, KTOT, nBase, (s + 2) * 32, nb + STAGE_H, tid);
            cpa_commit();
        } else {
            cpa_commit();   // keep group count in step with waits
        }
        const __half* Ab = hsm + sslot * SPAIR_H;
        const __half* Bb = Ab + STAGE_H;
#pragma unroll
        for (int ks = 0; ks < 2; ks++) {
            uint32_t afr[4][4];
#pragma unroll
            for (int mt = 0; mt < 4; mt++) {
                const __half* ap = Ab + (wm + mt * 16 + gid) * SPH + ks * 16 + 2 * tidx;
                afr[mt][0] = *(const uint32_t*)(ap);
                afr[mt][1] = *(const uint32_t*)(ap + 8 * SPH);
                afr[mt][2] = *(const uint32_t*)(ap + 8);
                afr[mt][3] = *(const uint32_t*)(ap + 8 * SPH + 8);
            }
#pragma unroll
            for (int nh = 0; nh < 2; nh++) {
                uint32_t bfr[4][2];
#pragma unroll
                for (int j = 0; j < 4; j++) {
                    const __half* bp = Bb + (wn + (nh * 4 + j) * 8 + gid) * SPH + ks * 16 + 2 * tidx;
                    bfr[j][0] = *(const uint32_t*)(bp);
                    bfr[j][1] = *(const uint32_t*)(bp + 8);
                }
#pragma unroll
                for (int mt = 0; mt < 4; mt++)
#pragma unroll
                    for (int j = 0; j < 4; j++)
                        mma_f16_16n8k16(acc[mt][nh * 4 + j], afr[mt], bfr[j]);
            }
        }
        if (++sslot == 3) sslot = 0;
    }
}

// ---------------- kernel 1: layernorm over C (writes half) ---------------------
__global__ void k_ln1(const float* __restrict__ x,
                      const float* __restrict__ lg, const float* __restrict__ lb)
{
    int b = blockIdx.y;
    int l = blockIdx.x * 128 + threadIdx.x;
    const float* xp = x + (size_t)b * Cch * Ls + l;
    float s = 0.f, s2 = 0.f;
#pragma unroll 8
    for (int c = 0; c < Cch; c++) { float v = xp[(size_t)c * Ls]; s += v; s2 += v * v; }
    float mu = s * (1.f / Cch);
    float rs = rsqrtf(s2 * (1.f / Cch) - mu * mu + 1e-5f);
    __half* out = g_hxn + ((size_t)b * Ls + l) * Cch;
#pragma unroll 4
    for (int c = 0; c < Cch; c += 4) {
        float v0 = (xp[(size_t)(c + 0) * Ls] - mu) * rs * lg[c + 0] + lb[c + 0];
        float v1 = (xp[(size_t)(c + 1) * Ls] - mu) * rs * lg[c + 1] + lb[c + 1];
        float v2 = (xp[(size_t)(c + 2) * Ls] - mu) * rs * lg[c + 2] + lb[c + 2];
        float v3 = (xp[(size_t)(c + 3) * Ls] - mu) * rs * lg[c + 3] + lb[c + 3];
        __half2 h01 = __floats2half2_rn(v0, v1);
        __half2 h23 = __floats2half2_rn(v2, v3);
        *(__half2*)(out + c)     = h01;
        *(__half2*)(out + c + 2) = h23;
    }
}

// ---------------- kernel 2: partial column sums -------------------------------
__global__ void k_zsum()
{
    int b = blockIdx.y, k = blockIdx.x, c = threadIdx.x;
    const __half* p = g_hxn + ((size_t)b * Ls + k * 128) * Cch + c;
    float s = 0.f;
#pragma unroll 8
    for (int i = 0; i < 128; i++) s += __half2float(p[(size_t)i * Cch]);
    g_zp[(k * Bsz + b) * Cch + c] = s;
}

// ---------------- kernel 3: gate MLP (one block per batch) ---------------------
__global__ void __launch_bounds__(256) k_gate(const float* __restrict__ fc1w,
                                              const float* __restrict__ fc1b,
                                              const float* __restrict__ fc2w,
                                              const float* __restrict__ fc2b)
{
    __shared__ float zsm[512];
    __shared__ float hsm[32];
    int t = threadIdx.x, b = blockIdx.x;
    int warp = t >> 5, lane = t & 31;
    for (int c = t; c < 512; c += 256) {
        float s = 0.f;
#pragma unroll
        for (int k = 0; k < 32; k++) s += g_zp[(k * Bsz + b) * 512 + c];
        zsm[c] = s * (1.f / Ls);
    }
    __syncthreads();
    for (int r = warp; r < 32; r += 8) {
        float p = 0.f;
#pragma unroll 4
        for (int i = lane; i < 512; i += 32) p += zsm[i] * fc1w[r * 512 + i];
#pragma unroll
        for (int o = 16; o; o >>= 1) p += __shfl_xor_sync(0xffffffffu, p, o);
        if (lane == 0) hsm[r] = fmaxf(p + fc1b[r], 0.f);
    }
    __syncthreads();
    for (int c = t; c < 512; c += 256) {
        float s = fc2b[c];
#pragma unroll
        for (int r = 0; r < 32; r++) s += hsm[r] * fc2w[c * 32 + r];
        g_gate[b * 512 + c] = 1.f / (1.f + expf(-s));
    }
}

// ---------------- weight rounding (fp16 RNE) ------------------------------------
__global__ void k_roundw(const float* __restrict__ ipw, const float* __restrict__ opw,
                         const float* __restrict__ pw)
{
    int i = blockIdx.x * 256 + threadIdx.x;
    if (i < Gg * 256 * 128) g_ipw[i] = __float2half_rn(ipw[i]);
    if (i < Gg * 128 * 128) g_opw[i] = __float2half_rn(opw[i]);
    if (i < 512 * 512)      g_pw[i]  = __float2half_rn(pw[i]);
}

// ---------------- GEMM 1: in_proj (fused SiLU on z half) ------------------------
__global__ void __launch_bounds__(128) k_gemm_in_mma()
{
    int g = blockIdx.z;
    int mBase = blockIdx.x * 128, nBase = blockIdx.y * 128;
    float acc[4][8][4] = {};
    mma_gemm_h<4>(g_hxn + g * 128, Cch, g_ipw + (size_t)g * 256 * 128,
                  mBase, nBase, acc);
    int lane = threadIdx.x & 31, wid = threadIdx.x >> 5;
    int gid = lane >> 2, tidx = lane & 3;
    int wm = (wid & 1) * 64, wn = (wid >> 1) * 64;
    bool dosilu = (nBase >= 128);
    float* Cp = g_xz + (size_t)g * Mrows * 256;
#pragma unroll
    for (int mt = 0; mt < 4; mt++)
#pragma unroll
    for (int half = 0; half < 2; half++) {
        int m = mBase + wm + mt * 16 + gid + half * 8;
        float* dst = Cp + (size_t)m * 256 + nBase + wn + 2 * tidx;
#pragma unroll
        for (int nt = 0; nt < 8; nt++) {
            float v0 = acc[mt][nt][half * 2], v1 = acc[mt][nt][half * 2 + 1];
            if (dosilu) { v0 = v0 / (1.f + expf(-v0)); v1 = v1 / (1.f + expf(-v1)); }
            float2 o = { v0, v1 };
            *(float2*)(dst + nt * 8) = o;
        }
    }
}

// ---------------- GEMM 2: out_proj ----------------------------------------------
__global__ void __launch_bounds__(128) k_gemm_out_mma()
{
    int g = blockIdx.z;
    int mBase = blockIdx.x * 128;
    float acc[4][8][4] = {};
    mma_gemm_h<4>(g_hyz + (size_t)g * Mrows * 128, 128, g_opw + (size_t)g * 128 * 128,
                  mBase, 0, acc);
    int lane = threadIdx.x & 31, wid = threadIdx.x >> 5;
    int gid = lane >> 2, tidx = lane & 3;
    int wm = (wid & 1) * 64, wn = (wid >> 1) * 64;
#pragma unroll
    for (int mt = 0; mt < 4; mt++)
#pragma unroll
    for (int half = 0; half < 2; half++) {
        int m = mBase + wm + mt * 16 + gid + half * 8;
        float* dst = g_ycat + (size_t)m * 512 + g * 128 + wn + 2 * tidx;
#pragma unroll
        for (int nt = 0; nt < 8; nt++) {
            float2 o = { acc[mt][nt][half * 2], acc[mt][nt][half * 2 + 1] };
            *(float2*)(dst + nt * 8) = o;
        }
    }
}

// ---------------- GEMM 3: final proj (transposed store + bias) -------------------
__global__ void __launch_bounds__(128) k_gemm_fin_mma(const float* __restrict__ pb,
                                                      float* __restrict__ out)
{
    int mBase = blockIdx.x * 128, nBase = blockIdx.y * 128;
    float acc[4][8][4] = {};
    mma_gemm_h<16>(g_hxmn, 512, g_pw, mBase, nBase, acc);
    int lane = threadIdx.x & 31, wid = threadIdx.x >> 5;
    int gid = lane >> 2, tidx = lane & 3;
    int wm = (wid & 1) * 64, wn = (wid >> 1) * 64;
#pragma unroll
    for (int mt = 0; mt < 4; mt++)
#pragma unroll
    for (int half = 0; half < 2; half++) {
        int m = mBase + wm + mt * 16 + gid + half * 8;
        int b = m >> 12, l = m & 4095;
#pragma unroll
        for (int nt = 0; nt < 8; nt++) {
            int n = nBase + wn + nt * 8 + 2 * tidx;
            out[((size_t)(b * 512 + n)) * 4096 + l]     = acc[mt][nt][half * 2]     + __ldg(pb + n);
            out[((size_t)(b * 512 + n + 1)) * 4096 + l] = acc[mt][nt][half * 2 + 1] + __ldg(pb + n + 1);
        }
    }
}

// ---------------- kernel 5: depthwise conv + silu + cross_scan -----------------
__global__ void __launch_bounds__(256) k_conv(const float* __restrict__ cw,
                                              const float* __restrict__ cb)
{
    __shared__ float sx[324 * 32];
    __shared__ float wsm[32 * 9];
    __shared__ float bsm[32];
    int tile = blockIdx.x, dt = blockIdx.y, gb = blockIdx.z;
    int g = gb >> 3, b = gb & 7;
    int h0 = (tile >> 2) * 16, w0 = (tile & 3) * 16;
    int dbase = dt * 32;
    int tid = threadIdx.x;
    const float* src = g_xz + ((size_t)g * Mrows + b * Ls) * 256;
    for (int idx = tid; idx < 324 * 32; idx += 256) {
        int pos = idx >> 5, dd = idx & 31;
        int h = h0 + pos / 18 - 1, w = w0 + pos % 18 - 1;
        float v = 0.f;
        if (h >= 0 && h < 64 && w >= 0 && w < 64)
            v = src[(size_t)(h * 64 + w) * 256 + dbase + dd];
        sx[idx] = v;
    }
    for (int i = tid; i < 288; i += 256)
        wsm[i] = cw[(size_t)(g * 128 + dbase + i / 9) * 9 + i % 9];
    if (tid < 32)  bsm[tid] = cb[g * 128 + dbase + tid];
    __syncthreads();
    int dd = tid & 31;
    float* dstbase = g_u + ((size_t)g * Mrows + b * Ls) * 128 + dbase + dd;
#pragma unroll 4
    for (int it = 0; it < 32; it++) {
        int pos = it * 8 + (tid >> 5);
        int ph = pos >> 4, pw = pos & 15;
        float acc = bsm[dd];
#pragma unroll
        for (int kh = 0; kh < 3; kh++)
#pragma unroll
            for (int kw = 0; kw < 3; kw++)
                acc += sx[((ph + kh) * 18 + pw + kw) * 32 + dd] * wsm[dd * 9 + kh * 3 + kw];
        acc = acc / (1.f + expf(-acc));
        int h = h0 + ph, w = w0 + pw;
        int lp;
        if (g == 0)      lp = h * 64 + w;
        else if (g == 1) lp = w * 64 + h;
        else if (g == 2) lp = 4095 - (h * 64 + w);
        else             lp = 4095 - (w * 64 + h);
        dstbase[(size_t)lp * 128] = acc;
    }
}

// ---------------- kernel 6: x_proj + dt_proj + dA/dBu/C + chunk scan summary ---
__global__ void __launch_bounds__(256) k_proj(const float* __restrict__ xpw,
                                              const float* __restrict__ dtw_g,
                                              const float* __restrict__ dtb_g,
                                              const float* __restrict__ alog)
{
    __shared__ float xp[10 * 128];
    __shared__ float dtwT[8 * 128];
    __shared__ float dtb[128];
    __shared__ float An[128];
    __shared__ float sP[8][128], sH[8][128];
    int tid = threadIdx.x, lane = tid & 31, warp = tid >> 5;
    int chunk0 = blockIdx.x * 8;
    int g = chunk0 >> 12;
    for (int i = tid; i < 1280; i += 256) xp[i] = xpw[(size_t)g * 1280 + i];
    for (int i = tid; i < 1024; i += 256) {
        int r = i >> 7, d = i & 127;
        dtwT[i] = dtw_g[(size_t)(g * 128 + d) * 8 + r];
    }
    if (tid < 128) { dtb[tid] = dtb_g[g * 128 + tid]; An[tid] = -expf(alog[g * 128 + tid]); }
    __syncthreads();
    int chunk = chunk0 + warp;
    int b = (chunk >> 9) & 7;
    int lp0 = (chunk & 511) * 8;
    size_t rowbase = (size_t)(g * 8 + b) * 4096 + lp0;
    float hseg[4] = {0.f, 0.f, 0.f, 0.f};
    float Pseg[4] = {1.f, 1.f, 1.f, 1.f};
    for (int it = 0; it < 8; it++) {
        size_t row = rowbase + it;
        float4 u4 = *(const float4*)(g_u + row * 128 + lane * 4);
        float xdbl[10];
#pragma unroll
        for (int c = 0; c < 10; c++) {
            const float* xc = xp + c * 128 + lane * 4;
            float p = u4.x * xc[0] + u4.y * xc[1] + u4.z * xc[2] + u4.w * xc[3];
#pragma unroll
            for (int o = 16; o; o >>= 1) p += __shfl_xor_sync(0xffffffffu, p, o);
            xdbl[c] = p;
        }
        float Bm = xdbl[8];
        float uarr[4] = { u4.x, u4.y, u4.z, u4.w };
        float dA4[4], db4[4];
#pragma unroll
        for (int j = 0; j < 4; j++) {
            int d = lane * 4 + j;
            float s = dtb[d];
#pragma unroll
            for (int r = 0; r < 8; r++) s += xdbl[r] * dtwT[r * 128 + d];
            float delta = (s > 20.f) ? s : log1pf(expf(s));
            dA4[j] = expf(delta * An[d]);
            db4[j] = delta * uarr[j] * Bm;
            hseg[j] = fmaf(dA4[j], hseg[j], db4[j]);
            Pseg[j] *= dA4[j];
        }
        *(float4*)(g_dA  + row * 128 + lane * 4) = *(float4*)dA4;
        *(float4*)(g_dbu + row * 128 + lane * 4) = *(float4*)db4;
        if (lane == 0) g_Cv[row] = xdbl[9];
    }
#pragma unroll
    for (int j = 0; j < 4; j++) { sP[warp][lane * 4 + j] = Pseg[j]; sH[warp][lane * 4 + j] = hseg[j]; }
    __syncthreads();
    if (tid < 128) {
        int d = tid;
        float h = 0.f, P = 1.f;
#pragma unroll
        for (int w = 0; w < 8; w++) {
            h = fmaf(sP[w][d], h, sH[w][d]);
            P *= sP[w][d];
        }
        int gb = g * 8 + b;
        int ch = (chunk0 & 511) >> 3;
        size_t o = ((size_t)gb * 64 + ch) * 128 + d;
        g_P[o] = P; g_hc[o] = h;
    }
}

// ---------------- kernel 7: inter-chunk serial scan ------------------------------
__global__ void k_scanB()
{
    int gb = blockIdx.x, d = threadIdx.x;
    float h = 0.f;
    for (int ch = 0; ch < 64; ch++) {
        size_t o = ((size_t)gb * 64 + ch) * 128 + d;
        g_hin[o] = h;
        h = fmaf(g_P[o], h, g_hc[o]);
    }
}

// ---------------- kernel 8: scanC fused with cross_merge + LN(D) + *z -----------
__global__ void __launch_bounds__(128) k_scanC_merge(const float* __restrict__ Dsp,
                                                     const float* __restrict__ og_,
                                                     const float* __restrict__ ob_)
{
    __shared__ float sS[2][4], sQ[2][4];
    int chunk = blockIdx.x, gb = blockIdx.y, d = threadIdx.x;
    int g = gb >> 3;
    int lane = d & 31, warp = d >> 5;
    float Ds  = Dsp[g * 128 + d];
    float ogv = og_[g * 128 + d];
    float obv = ob_[g * 128 + d];
    size_t base = ((size_t)gb * 4096 + chunk * 64) * 128 + d;
    size_t crow = (size_t)gb * 4096 + chunk * 64;
    float h = g_hin[((size_t)gb * 64 + chunk) * 128 + d];
    for (int i = 0; i < 64; i++) {
        size_t idx = base + (size_t)i * 128;
        h = fmaf(g_dA[idx], h, g_dbu[idx]);
        float yv = h * g_Cv[crow + i] + Ds * g_u[idx];
        float s = yv, q = yv * yv;
#pragma unroll
        for (int o = 16; o; o >>= 1) {
            s += __shfl_xor_sync(0xffffffffu, s, o);
            q += __shfl_xor_sync(0xffffffffu, q, o);
        }
        int slot = i & 1;
        if (lane == 0) { sS[slot][warp] = s; sQ[slot][warp] = q; }
        __syncthreads();
        s = sS[slot][0] + sS[slot][1] + sS[slot][2] + sS[slot][3];
        q = sQ[slot][0] + sQ[slot][1] + sQ[slot][2] + sQ[slot][3];
        float mu = s * (1.f / 128.f);
        float rs = rsqrtf(q * (1.f / 128.f) - mu * mu + 1e-5f);
        int lp = chunk * 64 + i;
        int l;
        if (g == 0)      l = lp;
        else if (g == 1) l = (lp & 63) * 64 + (lp >> 6);
        else if (g == 2) l = 4095 - lp;
        else { int t2 = 4095 - lp; l = (t2 & 63) * 64 + (t2 >> 6); }
        size_t drow = (size_t)gb * 4096 + l;
        float z = g_xz[drow * 256 + 128 + d];
        g_hyz[drow * 128 + d] = __float2half_rn(((yv - mu) * rs * ogv + obv) * z);
    }
}

// ---------------- kernel 12: mix + gate + LN(C) ---------------------------------
__global__ void __launch_bounds__(128) k_premix(const float* __restrict__ lg,
                                                const float* __restrict__ lb,
                                                const float* __restrict__ skip)
{
    int row = blockIdx.x, b = row >> 12, tid = threadIdx.x;
    float sk = skip[0];
    float4 yc = *(const float4*)(g_ycat + (size_t)row * 512 + tid * 4);
    const __half2* xnp = (const __half2*)(g_hxn + (size_t)row * 512 + tid * 4);
    float2 x01 = __half22float2(xnp[0]);
    float2 x23 = __half22float2(xnp[1]);
    float4 gt = *(const float4*)(g_gate + (size_t)b * 512 + tid * 4);
    float v[4] = { yc.x * sk * x01.x * gt.x, yc.y * sk * x01.y * gt.y,
                   yc.z * sk * x23.x * gt.z, yc.w * sk * x23.y * gt.w };
    float s  = v[0] + v[1] + v[2] + v[3];
    float s2 = v[0] * v[0] + v[1] * v[1] + v[2] * v[2] + v[3] * v[3];
#pragma unroll
    for (int o = 16; o; o >>= 1) {
        s  += __shfl_xor_sync(0xffffffffu, s, o);
        s2 += __shfl_xor_sync(0xffffffffu, s2, o);
    }
    __shared__ float rs_[4], rq_[4];
    int warp = tid >> 5, lane = tid & 31;
    if (lane == 0) { rs_[warp] = s; rq_[warp] = s2; }
    __syncthreads();
    s  = rs_[0] + rs_[1] + rs_[2] + rs_[3];
    s2 = rq_[0] + rq_[1] + rq_[2] + rq_[3];
    float mu = s * (1.f / 512.f);
    float rstd = rsqrtf(s2 * (1.f / 512.f) - mu * mu + 1e-5f);
    __half2 o01 = __floats2half2_rn((v[0] - mu) * rstd * lg[tid * 4 + 0] + lb[tid * 4 + 0],
                                    (v[1] - mu) * rstd * lg[tid * 4 + 1] + lb[tid * 4 + 1]);
    __half2 o23 = __floats2half2_rn((v[2] - mu) * rstd * lg[tid * 4 + 2] + lb[tid * 4 + 2],
                                    (v[3] - mu) * rstd * lg[tid * 4 + 3] + lb[tid * 4 + 3]);
    __half2* outp = (__half2*)(g_hxmn + (size_t)row * 512 + tid * 4);
    outp[0] = o01; outp[1] = o23;
}

// ---------------- launch ---------------------------------------------------------
extern "C" void kernel_launch(void* const* d_in, const int* in_sizes, int n_in,
                              void* d_out, int out_size)
{
    const float* x    = (const float*)d_in[0];
    const float* ln_g = (const float*)d_in[1];
    const float* ln_b = (const float*)d_in[2];
    const float* fc1w = (const float*)d_in[3];
    const float* fc1b = (const float*)d_in[4];
    const float* fc2w = (const float*)d_in[5];
    const float* fc2b = (const float*)d_in[6];
    const float* ipw  = (const float*)d_in[7];
    const float* cw   = (const float*)d_in[8];
    const float* cb   = (const float*)d_in[9];
    const float* xpw  = (const float*)d_in[10];
    const float* dtw  = (const float*)d_in[11];
    const float* dtb  = (const float*)d_in[12];
    const float* alog = (const float*)d_in[13];
    const float* dsp  = (const float*)d_in[14];
    const float* ong  = (const float*)d_in[15];
    const float* onb  = (const float*)d_in[16];
    const float* opw  = (const float*)d_in[17];
    const float* pw   = (const float*)d_in[18];
    const float* pb   = (const float*)d_in[19];
    const float* skip = (const float*)d_in[20];
    float* out = (float*)d_out;

    cudaFuncSetAttribute(k_gemm_in_mma,  cudaFuncAttributeMaxDynamicSharedMemorySize, GEMM_SMEM3);
    cudaFuncSetAttribute(k_gemm_out_mma, cudaFuncAttributeMaxDynamicSharedMemorySize, GEMM_SMEM3);
    cudaFuncSetAttribute(k_gemm_fin_mma, cudaFuncAttributeMaxDynamicSharedMemorySize, GEMM_SMEM3);

    // (gemm_in placed 4th so the profiler's captured launch is the GEMM core)
    k_ln1         <<<dim3(32, 8),     128>>>(x, ln_g, ln_b);
    k_roundw      <<<1024,            256>>>(ipw, opw, pw);
    k_zsum        <<<dim3(32, 8),     512>>>();
    k_gemm_in_mma <<<dim3(256, 2, 4), 128, GEMM_SMEM3>>>();
    k_gate        <<<8,               256>>>(fc1w, fc1b, fc2w, fc2b);
    k_conv        <<<dim3(16, 4, 32), 256>>>(cw, cb);
    k_proj        <<<2048,            256>>>(xpw, dtw, dtb, alog);
    k_scanB       <<<32,              128>>>();
    k_scanC_merge <<<dim3(64, 32),    128>>>(dsp, ong, onb);
    k_gemm_out_mma<<<dim3(256, 1, 4), 128, GEMM_SMEM3>>>();
    k_premix      <<<32768,           128>>>(ln_g, ln_b, skip);
    k_gemm_fin_mma<<<dim3(256, 4),    128, GEMM_SMEM3>>>(pb, out);
}

// round 16
// speedup vs baseline: 1.2094x; 1.0214x over previous
#include <cuda_runtime.h>
#include <cuda_fp16.h>
#include <math.h>
#include <stdint.h>

// Problem constants
#define Bsz 8
#define Cch 512
#define Ls 4096
#define Gg 4
#define Dd 128
#define Mrows 32768   // B*L

// ---------------- scratch (device globals; no cudaMalloc allowed) -------------
__device__ __half g_hxn [(size_t)Bsz*Ls*Cch];      // LN1 output (half)
__device__ float  g_zp  [32*Bsz*Cch];
__device__ float  g_gate[Bsz*Cch];
__device__ __half g_hxd [(size_t)Gg*Mrows*Dd];     // in_proj xd half (pre-conv)
__device__ __half g_hz  [(size_t)Gg*Mrows*Dd];     // silu(z) half
__device__ float  g_u   [(size_t)Gg*Mrows*Dd];
__device__ float  g_dA  [(size_t)Gg*Mrows*Dd];
__device__ float  g_dbu [(size_t)Gg*Mrows*Dd];
__device__ float  g_Cv  [Gg*Mrows];
__device__ float  g_P   [Gg*Bsz*64*Dd];
__device__ float  g_hc  [Gg*Bsz*64*Dd];
__device__ float  g_hin [Gg*Bsz*64*Dd];
__device__ __half g_hyz [(size_t)Gg*Mrows*Dd];     // merged LN*z (half)
__device__ float  g_ycat[(size_t)Mrows*Cch];
__device__ __half g_hxmn[(size_t)Mrows*Cch];       // premix output (half)
// fp16-rounded weight copies
__device__ __half g_ipw [Gg*256*128];
__device__ __half g_opw [Gg*128*128];
__device__ __half g_pw  [512*512];

// ---------------- helpers -------------------------------------------------------
__device__ __forceinline__ uint32_t sm_u32(const void* p) {
    return (uint32_t)__cvta_generic_to_shared(p);
}
__device__ __forceinline__ void cpa16(uint32_t dst, const void* src) {
    asm volatile("cp.async.cg.shared.global [%0], [%1], 16;" :: "r"(dst), "l"(src));
}
__device__ __forceinline__ void cpa_commit() { asm volatile("cp.async.commit_group;"); }
template<int N> __device__ __forceinline__ void cpa_wait() {
    asm volatile("cp.async.wait_group %0;" :: "n"(N));
}
__device__ __forceinline__ void mma_f16_16n8k16(float* c, const uint32_t* a, const uint32_t* b) {
    asm volatile(
        "mma.sync.aligned.m16n8k16.row.col.f32.f16.f16.f32 "
        "{%0,%1,%2,%3}, {%4,%5,%6,%7}, {%8,%9}, {%0,%1,%2,%3};"
        : "+f"(c[0]), "+f"(c[1]), "+f"(c[2]), "+f"(c[3])
        : "r"(a[0]), "r"(a[1]), "r"(a[2]), "r"(a[3]), "r"(b[0]), "r"(b[1]));
}

// SMEM stage: 128 rows x 32 halves, pitch 40 halves (20 words -> conflict-free)
#define SPH 40
#define STAGE_H (128 * SPH)
#define SPAIR_H (2 * STAGE_H)
#define GEMM_SMEM3 (3 * SPAIR_H * 2)   // 61440 bytes

__device__ __forceinline__ void stage_load_h(const __half* __restrict__ g, int ld,
                                             int r0, int k0, __half* sbuf, int tid)
{
#pragma unroll
    for (int i = 0; i < 4; i++) {
        int s = tid + (i << 7);
        int r = s >> 2, seg = s & 3;
        cpa16(sm_u32(sbuf + r * SPH + seg * 8),
              g + (size_t)(r0 + r) * ld + k0 + seg * 8);
    }
}

// ---------------- fp16 mma.sync 128x128xK core (4 warps, 64x64 warp tile) -------
template<int S>   // S = K/32 stages
__device__ __forceinline__ void mma_gemm_h(const __half* __restrict__ Ag, int lda,
                                           const __half* __restrict__ Bg,
                                           int mBase, int nBase,
                                           float acc[4][8][4])
{
    extern __shared__ __align__(16) char smraw[];
    __half* hsm = (__half*)smraw;
    const int KTOT = 32 * S;
    int tid = threadIdx.x, wid = tid >> 5, lane = tid & 31;
    int gid = lane >> 2, tidx = lane & 3;
    int wm = (wid & 1) * 64, wn = (wid >> 1) * 64;

    stage_load_h(Ag, lda, mBase, 0, hsm, tid);
    stage_load_h(Bg, KTOT, nBase, 0, hsm + STAGE_H, tid);
    cpa_commit();
    if (S > 1) {
        stage_load_h(Ag, lda, mBase, 32, hsm + SPAIR_H, tid);
        stage_load_h(Bg, KTOT, nBase, 32, hsm + SPAIR_H + STAGE_H, tid);
    }
    cpa_commit();

    int sslot = 0;
    for (int s = 0; s < S; s++) {
        if (s + 1 < S) cpa_wait<1>(); else cpa_wait<0>();
        __syncthreads();
        if (s + 2 < S) {
            int ns = sslot + 2; if (ns >= 3) ns -= 3;
            __half* nb = hsm + ns * SPAIR_H;
            stage_load_h(Ag, lda, mBase, (s + 2) * 32, nb, tid);
            stage_load_h(Bg, KTOT, nBase, (s + 2) * 32, nb + STAGE_H, tid);
            cpa_commit();
        } else {
            cpa_commit();
        }
        const __half* Ab = hsm + sslot * SPAIR_H;
        const __half* Bb = Ab + STAGE_H;
#pragma unroll
        for (int ks = 0; ks < 2; ks++) {
            uint32_t afr[4][4];
#pragma unroll
            for (int mt = 0; mt < 4; mt++) {
                const __half* ap = Ab + (wm + mt * 16 + gid) * SPH + ks * 16 + 2 * tidx;
                afr[mt][0] = *(const uint32_t*)(ap);
                afr[mt][1] = *(const uint32_t*)(ap + 8 * SPH);
                afr[mt][2] = *(const uint32_t*)(ap + 8);
                afr[mt][3] = *(const uint32_t*)(ap + 8 * SPH + 8);
            }
#pragma unroll
            for (int nh = 0; nh < 2; nh++) {
                uint32_t bfr[4][2];
#pragma unroll
                for (int j = 0; j < 4; j++) {
                    const __half* bp = Bb + (wn + (nh * 4 + j) * 8 + gid) * SPH + ks * 16 + 2 * tidx;
                    bfr[j][0] = *(const uint32_t*)(bp);
                    bfr[j][1] = *(const uint32_t*)(bp + 8);
                }
#pragma unroll
                for (int mt = 0; mt < 4; mt++)
#pragma unroll
                    for (int j = 0; j < 4; j++)
                        mma_f16_16n8k16(acc[mt][nh * 4 + j], afr[mt], bfr[j]);
            }
        }
        if (++sslot == 3) sslot = 0;
    }
}

// ---------------- kernel 1: layernorm over C (writes half) ---------------------
__global__ void k_ln1(const float* __restrict__ x,
                      const float* __restrict__ lg, const float* __restrict__ lb)
{
    int b = blockIdx.y;
    int l = blockIdx.x * 128 + threadIdx.x;
    const float* xp = x + (size_t)b * Cch * Ls + l;
    float s = 0.f, s2 = 0.f;
#pragma unroll 8
    for (int c = 0; c < Cch; c++) { float v = xp[(size_t)c * Ls]; s += v; s2 += v * v; }
    float mu = s * (1.f / Cch);
    float rs = rsqrtf(s2 * (1.f / Cch) - mu * mu + 1e-5f);
    __half* out = g_hxn + ((size_t)b * Ls + l) * Cch;
#pragma unroll 4
    for (int c = 0; c < Cch; c += 4) {
        float v0 = (xp[(size_t)(c + 0) * Ls] - mu) * rs * lg[c + 0] + lb[c + 0];
        float v1 = (xp[(size_t)(c + 1) * Ls] - mu) * rs * lg[c + 1] + lb[c + 1];
        float v2 = (xp[(size_t)(c + 2) * Ls] - mu) * rs * lg[c + 2] + lb[c + 2];
        float v3 = (xp[(size_t)(c + 3) * Ls] - mu) * rs * lg[c + 3] + lb[c + 3];
        *(__half2*)(out + c)     = __floats2half2_rn(v0, v1);
        *(__half2*)(out + c + 2) = __floats2half2_rn(v2, v3);
    }
}

// ---------------- kernel 2: partial column sums -------------------------------
__global__ void k_zsum()
{
    int b = blockIdx.y, k = blockIdx.x, c = threadIdx.x;
    const __half* p = g_hxn + ((size_t)b * Ls + k * 128) * Cch + c;
    float s = 0.f;
#pragma unroll 8
    for (int i = 0; i < 128; i++) s += __half2float(p[(size_t)i * Cch]);
    g_zp[(k * Bsz + b) * Cch + c] = s;
}

// ---------------- kernel 3: gate MLP (one block per batch) ---------------------
__global__ void __launch_bounds__(256) k_gate(const float* __restrict__ fc1w,
                                              const float* __restrict__ fc1b,
                                              const float* __restrict__ fc2w,
                                              const float* __restrict__ fc2b)
{
    __shared__ float zsm[512];
    __shared__ float hsm[32];
    int t = threadIdx.x, b = blockIdx.x;
    int warp = t >> 5, lane = t & 31;
    for (int c = t; c < 512; c += 256) {
        float s = 0.f;
#pragma unroll
        for (int k = 0; k < 32; k++) s += g_zp[(k * Bsz + b) * 512 + c];
        zsm[c] = s * (1.f / Ls);
    }
    __syncthreads();
    for (int r = warp; r < 32; r += 8) {
        float p = 0.f;
#pragma unroll 4
        for (int i = lane; i < 512; i += 32) p += zsm[i] * fc1w[r * 512 + i];
#pragma unroll
        for (int o = 16; o; o >>= 1) p += __shfl_xor_sync(0xffffffffu, p, o);
        if (lane == 0) hsm[r] = fmaxf(p + fc1b[r], 0.f);
    }
    __syncthreads();
    for (int c = t; c < 512; c += 256) {
        float s = fc2b[c];
#pragma unroll
        for (int r = 0; r < 32; r++) s += hsm[r] * fc2w[c * 32 + r];
        g_gate[b * 512 + c] = 1.f / (1.f + expf(-s));
    }
}

// ---------------- weight rounding (fp16 RNE) ------------------------------------
__global__ void k_roundw(const float* __restrict__ ipw, const float* __restrict__ opw,
                         const float* __restrict__ pw)
{
    int i = blockIdx.x * 256 + threadIdx.x;
    if (i < Gg * 256 * 128) g_ipw[i] = __float2half_rn(ipw[i]);
    if (i < Gg * 128 * 128) g_opw[i] = __float2half_rn(opw[i]);
    if (i < 512 * 512)      g_pw[i]  = __float2half_rn(pw[i]);
}

// ---------------- GEMM 1: in_proj (xd half / silu(z) half) ----------------------
__global__ void __launch_bounds__(128) k_gemm_in_mma()
{
    int g = blockIdx.z;
    int mBase = blockIdx.x * 128, nBase = blockIdx.y * 128;
    float acc[4][8][4] = {};
    mma_gemm_h<4>(g_hxn + g * 128, Cch, g_ipw + (size_t)g * 256 * 128,
                  mBase, nBase, acc);
    int lane = threadIdx.x & 31, wid = threadIdx.x >> 5;
    int gid = lane >> 2, tidx = lane & 3;
    int wm = (wid & 1) * 64, wn = (wid >> 1) * 64;
    bool dosilu = (nBase >= 128);
    __half* Cp = (dosilu ? g_hz : g_hxd) + (size_t)g * Mrows * 128;
#pragma unroll
    for (int mt = 0; mt < 4; mt++)
#pragma unroll
    for (int half = 0; half < 2; half++) {
        int m = mBase + wm + mt * 16 + gid + half * 8;
        __half* dst = Cp + (size_t)m * 128 + wn + 2 * tidx;
#pragma unroll
        for (int nt = 0; nt < 8; nt++) {
            float v0 = acc[mt][nt][half * 2], v1 = acc[mt][nt][half * 2 + 1];
            if (dosilu) { v0 = v0 / (1.f + expf(-v0)); v1 = v1 / (1.f + expf(-v1)); }
            *(__half2*)(dst + nt * 8) = __floats2half2_rn(v0, v1);
        }
    }
}

// ---------------- GEMM 2: out_proj ----------------------------------------------
__global__ void __launch_bounds__(128) k_gemm_out_mma()
{
    int g = blockIdx.z;
    int mBase = blockIdx.x * 128;
    float acc[4][8][4] = {};
    mma_gemm_h<4>(g_hyz + (size_t)g * Mrows * 128, 128, g_opw + (size_t)g * 128 * 128,
                  mBase, 0, acc);
    int lane = threadIdx.x & 31, wid = threadIdx.x >> 5;
    int gid = lane >> 2, tidx = lane & 3;
    int wm = (wid & 1) * 64, wn = (wid >> 1) * 64;
#pragma unroll
    for (int mt = 0; mt < 4; mt++)
#pragma unroll
    for (int half = 0; half < 2; half++) {
        int m = mBase + wm + mt * 16 + gid + half * 8;
        float* dst = g_ycat + (size_t)m * 512 + g * 128 + wn + 2 * tidx;
#pragma unroll
        for (int nt = 0; nt < 8; nt++) {
            float2 o = { acc[mt][nt][half * 2], acc[mt][nt][half * 2 + 1] };
            *(float2*)(dst + nt * 8) = o;
        }
    }
}

// ---------------- GEMM 3: final proj (transposed store + bias) -------------------
__global__ void __launch_bounds__(128) k_gemm_fin_mma(const float* __restrict__ pb,
                                                      float* __restrict__ out)
{
    int mBase = blockIdx.x * 128, nBase = blockIdx.y * 128;
    float acc[4][8][4] = {};
    mma_gemm_h<16>(g_hxmn, 512, g_pw, mBase, nBase, acc);
    int lane = threadIdx.x & 31, wid = threadIdx.x >> 5;
    int gid = lane >> 2, tidx = lane & 3;
    int wm = (wid & 1) * 64, wn = (wid >> 1) * 64;
#pragma unroll
    for (int mt = 0; mt < 4; mt++)
#pragma unroll
    for (int half = 0; half < 2; half++) {
        int m = mBase + wm + mt * 16 + gid + half * 8;
        int b = m >> 12, l = m & 4095;
#pragma unroll
        for (int nt = 0; nt < 8; nt++) {
            int n = nBase + wn + nt * 8 + 2 * tidx;
            out[((size_t)(b * 512 + n)) * 4096 + l]     = acc[mt][nt][half * 2]     + __ldg(pb + n);
            out[((size_t)(b * 512 + n + 1)) * 4096 + l] = acc[mt][nt][half * 2 + 1] + __ldg(pb + n + 1);
        }
    }
}

// ---------------- kernel 5: depthwise conv + silu + cross_scan -----------------
__global__ void __launch_bounds__(256) k_conv(const float* __restrict__ cw,
                                              const float* __restrict__ cb)
{
    __shared__ float sx[324 * 32];
    __shared__ float wsm[32 * 9];
    __shared__ float bsm[32];
    int tile = blockIdx.x, dt = blockIdx.y, gb = blockIdx.z;
    int g = gb >> 3, b = gb & 7;
    int h0 = (tile >> 2) * 16, w0 = (tile & 3) * 16;
    int dbase = dt * 32;
    int tid = threadIdx.x;
    const __half* src = g_hxd + ((size_t)g * Mrows + b * Ls) * 128;
    for (int idx = tid; idx < 324 * 32; idx += 256) {
        int pos = idx >> 5, dd = idx & 31;
        int h = h0 + pos / 18 - 1, w = w0 + pos % 18 - 1;
        float v = 0.f;
        if (h >= 0 && h < 64 && w >= 0 && w < 64)
            v = __half2float(src[(size_t)(h * 64 + w) * 128 + dbase + dd]);
        sx[idx] = v;
    }
    for (int i = tid; i < 288; i += 256)
        wsm[i] = cw[(size_t)(g * 128 + dbase + i / 9) * 9 + i % 9];
    if (tid < 32)  bsm[tid] = cb[g * 128 + dbase + tid];
    __syncthreads();
    int dd = tid & 31;
    float* dstbase = g_u + ((size_t)g * Mrows + b * Ls) * 128 + dbase + dd;
#pragma unroll 4
    for (int it = 0; it < 32; it++) {
        int pos = it * 8 + (tid >> 5);
        int ph = pos >> 4, pw = pos & 15;
        float acc = bsm[dd];
#pragma unroll
        for (int kh = 0; kh < 3; kh++)
#pragma unroll
            for (int kw = 0; kw < 3; kw++)
                acc += sx[((ph + kh) * 18 + pw + kw) * 32 + dd] * wsm[dd * 9 + kh * 3 + kw];
        acc = acc / (1.f + expf(-acc));
        int h = h0 + ph, w = w0 + pw;
        int lp;
        if (g == 0)      lp = h * 64 + w;
        else if (g == 1) lp = w * 64 + h;
        else if (g == 2) lp = 4095 - (h * 64 + w);
        else             lp = 4095 - (w * 64 + h);
        dstbase[(size_t)lp * 128] = acc;
    }
}

// ---------------- kernel 6: x_proj + dt_proj + dA/dBu/C + chunk scan summary ---
__global__ void __launch_bounds__(256) k_proj(const float* __restrict__ xpw,
                                              const float* __restrict__ dtw_g,
                                              const float* __restrict__ dtb_g,
                                              const float* __restrict__ alog)
{
    __shared__ float xp[10 * 128];
    __shared__ float dtwT[8 * 128];
    __shared__ float dtb[128];
    __shared__ float An[128];
    __shared__ float sP[8][128], sH[8][128];
    int tid = threadIdx.x, lane = tid & 31, warp = tid >> 5;
    int chunk0 = blockIdx.x * 8;
    int g = chunk0 >> 12;
    for (int i = tid; i < 1280; i += 256) xp[i] = xpw[(size_t)g * 1280 + i];
    for (int i = tid; i < 1024; i += 256) {
        int r = i >> 7, d = i & 127;
        dtwT[i] = dtw_g[(size_t)(g * 128 + d) * 8 + r];
    }
    if (tid < 128) { dtb[tid] = dtb_g[g * 128 + tid]; An[tid] = -expf(alog[g * 128 + tid]); }
    __syncthreads();
    int chunk = chunk0 + warp;
    int b = (chunk >> 9) & 7;
    int lp0 = (chunk & 511) * 8;
    size_t rowbase = (size_t)(g * 8 + b) * 4096 + lp0;
    float hseg[4] = {0.f, 0.f, 0.f, 0.f};
    float Pseg[4] = {1.f, 1.f, 1.f, 1.f};
    for (int it = 0; it < 8; it++) {
        size_t row = rowbase + it;
        float4 u4 = *(const float4*)(g_u + row * 128 + lane * 4);
        float xdbl[10];
#pragma unroll
        for (int c = 0; c < 10; c++) {
            const float* xc = xp + c * 128 + lane * 4;
            float p = u4.x * xc[0] + u4.y * xc[1] + u4.z * xc[2] + u4.w * xc[3];
#pragma unroll
            for (int o = 16; o; o >>= 1) p += __shfl_xor_sync(0xffffffffu, p, o);
            xdbl[c] = p;
        }
        float Bm = xdbl[8];
        float uarr[4] = { u4.x, u4.y, u4.z, u4.w };
        float dA4[4], db4[4];
#pragma unroll
        for (int j = 0; j < 4; j++) {
            int d = lane * 4 + j;
            float s = dtb[d];
#pragma unroll
            for (int r = 0; r < 8; r++) s += xdbl[r] * dtwT[r * 128 + d];
            float delta = (s > 20.f) ? s : log1pf(expf(s));
            dA4[j] = expf(delta * An[d]);
            db4[j] = delta * uarr[j] * Bm;
            hseg[j] = fmaf(dA4[j], hseg[j], db4[j]);
            Pseg[j] *= dA4[j];
        }
        *(float4*)(g_dA  + row * 128 + lane * 4) = *(float4*)dA4;
        *(float4*)(g_dbu + row * 128 + lane * 4) = *(float4*)db4;
        if (lane == 0) g_Cv[row] = xdbl[9];
    }
#pragma unroll
    for (int j = 0; j < 4; j++) { sP[warp][lane * 4 + j] = Pseg[j]; sH[warp][lane * 4 + j] = hseg[j]; }
    __syncthreads();
    if (tid < 128) {
        int d = tid;
        float h = 0.f, P = 1.f;
#pragma unroll
        for (int w = 0; w < 8; w++) {
            h = fmaf(sP[w][d], h, sH[w][d]);
            P *= sP[w][d];
        }
        int gb = g * 8 + b;
        int ch = (chunk0 & 511) >> 3;
        size_t o = ((size_t)gb * 64 + ch) * 128 + d;
        g_P[o] = P; g_hc[o] = h;
    }
}

// ---------------- kernel 7: inter-chunk serial scan ------------------------------
__global__ void k_scanB()
{
    int gb = blockIdx.x, d = threadIdx.x;
    float h = 0.f;
    for (int ch = 0; ch < 64; ch++) {
        size_t o = ((size_t)gb * 64 + ch) * 128 + d;
        g_hin[o] = h;
        h = fmaf(g_P[o], h, g_hc[o]);
    }
}

// ---------------- kernel 8: scanC + merge, WARP-PER-CHUNK (no block barriers) ---
__global__ void __launch_bounds__(256) k_scanC_merge(const float* __restrict__ Dsp,
                                                     const float* __restrict__ og_,
                                                     const float* __restrict__ ob_)
{
    int gb = blockIdx.y;
    int warp = threadIdx.x >> 5, lane = threadIdx.x & 31;
    int chunk = blockIdx.x * 8 + warp;
    int g = gb >> 3;
    int d0 = lane * 4;
    float4 Ds4 = *(const float4*)(Dsp + g * 128 + d0);
    float4 og4 = *(const float4*)(og_ + g * 128 + d0);
    float4 ob4 = *(const float4*)(ob_ + g * 128 + d0);
    float Ds[4] = { Ds4.x, Ds4.y, Ds4.z, Ds4.w };
    float og[4] = { og4.x, og4.y, og4.z, og4.w };
    float ob[4] = { ob4.x, ob4.y, ob4.z, ob4.w };
    float4 h4 = *(const float4*)(g_hin + ((size_t)gb * 64 + chunk) * 128 + d0);
    float h[4] = { h4.x, h4.y, h4.z, h4.w };
    size_t base = ((size_t)gb * 4096 + chunk * 64) * 128 + d0;
    size_t crow = (size_t)gb * 4096 + chunk * 64;
#pragma unroll 2
    for (int i = 0; i < 64; i++) {
        size_t idx = base + (size_t)i * 128;
        float4 a4 = *(const float4*)(g_dA  + idx);
        float4 b4 = *(const float4*)(g_dbu + idx);
        float4 u4 = *(const float4*)(g_u   + idx);
        float Cv = g_Cv[crow + i];
        h[0] = fmaf(a4.x, h[0], b4.x);
        h[1] = fmaf(a4.y, h[1], b4.y);
        h[2] = fmaf(a4.z, h[2], b4.z);
        h[3] = fmaf(a4.w, h[3], b4.w);
        float yv[4] = { h[0] * Cv + Ds[0] * u4.x, h[1] * Cv + Ds[1] * u4.y,
                        h[2] * Cv + Ds[2] * u4.z, h[3] * Cv + Ds[3] * u4.w };
        float s = yv[0] + yv[1] + yv[2] + yv[3];
        float q = yv[0] * yv[0] + yv[1] * yv[1] + yv[2] * yv[2] + yv[3] * yv[3];
#pragma unroll
        for (int o = 16; o; o >>= 1) {
            s += __shfl_xor_sync(0xffffffffu, s, o);
            q += __shfl_xor_sync(0xffffffffu, q, o);
        }
        float mu = s * (1.f / 128.f);
        float rs = rsqrtf(q * (1.f / 128.f) - mu * mu + 1e-5f);
        int lp = chunk * 64 + i;
        int l;
        if (g == 0)      l = lp;
        else if (g == 1) l = (lp & 63) * 64 + (lp >> 6);
        else if (g == 2) l = 4095 - lp;
        else { int t2 = 4095 - lp; l = (t2 & 63) * 64 + (t2 >> 6); }
        size_t drow = (size_t)gb * 4096 + l;
        const __half2* zp = (const __half2*)(g_hz + drow * 128 + d0);
        float2 zA = __half22float2(zp[0]);
        float2 zB = __half22float2(zp[1]);
        __half2 o01 = __floats2half2_rn(((yv[0] - mu) * rs * og[0] + ob[0]) * zA.x,
                                        ((yv[1] - mu) * rs * og[1] + ob[1]) * zA.y);
        __half2 o23 = __floats2half2_rn(((yv[2] - mu) * rs * og[2] + ob[2]) * zB.x,
                                        ((yv[3] - mu) * rs * og[3] + ob[3]) * zB.y);
        __half2* outp = (__half2*)(g_hyz + drow * 128 + d0);
        outp[0] = o01; outp[1] = o23;
    }
}

// ---------------- kernel 12: mix + gate + LN(C) ---------------------------------
__global__ void __launch_bounds__(128) k_premix(const float* __restrict__ lg,
                                                const float* __restrict__ lb,
                                                const float* __restrict__ skip)
{
    int row = blockIdx.x, b = row >> 12, tid = threadIdx.x;
    float sk = skip[0];
    float4 yc = *(const float4*)(g_ycat + (size_t)row * 512 + tid * 4);
    const __half2* xnp = (const __half2*)(g_hxn + (size_t)row * 512 + tid * 4);
    float2 x01 = __half22float2(xnp[0]);
    float2 x23 = __half22float2(xnp[1]);
    float4 gt = *(const float4*)(g_gate + (size_t)b * 512 + tid * 4);
    float v[4] = { yc.x * sk * x01.x * gt.x, yc.y * sk * x01.y * gt.y,
                   yc.z * sk * x23.x * gt.z, yc.w * sk * x23.y * gt.w };
    float s  = v[0] + v[1] + v[2] + v[3];
    float s2 = v[0] * v[0] + v[1] * v[1] + v[2] * v[2] + v[3] * v[3];
#pragma unroll
    for (int o = 16; o; o >>= 1) {
        s  += __shfl_xor_sync(0xffffffffu, s, o);
        s2 += __shfl_xor_sync(0xffffffffu, s2, o);
    }
    __shared__ float rs_[4], rq_[4];
    int warp = tid >> 5, lane = tid & 31;
    if (lane == 0) { rs_[warp] = s; rq_[warp] = s2; }
    __syncthreads();
    s  = rs_[0] + rs_[1] + rs_[2] + rs_[3];
    s2 = rq_[0] + rq_[1] + rq_[2] + rq_[3];
    float mu = s * (1.f / 512.f);
    float rstd = rsqrtf(s2 * (1.f / 512.f) - mu * mu + 1e-5f);
    __half2 o01 = __floats2half2_rn((v[0] - mu) * rstd * lg[tid * 4 + 0] + lb[tid * 4 + 0],
                                    (v[1] - mu) * rstd * lg[tid * 4 + 1] + lb[tid * 4 + 1]);
    __half2 o23 = __floats2half2_rn((v[2] - mu) * rstd * lg[tid * 4 + 2] + lb[tid * 4 + 2],
                                    (v[3] - mu) * rstd * lg[tid * 4 + 3] + lb[tid * 4 + 3]);
    __half2* outp = (__half2*)(g_hxmn + (size_t)row * 512 + tid * 4);
    outp[0] = o01; outp[1] = o23;
}

// ---------------- launch ---------------------------------------------------------
extern "C" void kernel_launch(void* const* d_in, const int* in_sizes, int n_in,
                              void* d_out, int out_size)
{
    const float* x    = (const float*)d_in[0];
    const float* ln_g = (const float*)d_in[1];
    const float* ln_b = (const float*)d_in[2];
    const float* fc1w = (const float*)d_in[3];
    const float* fc1b = (const float*)d_in[4];
    const float* fc2w = (const float*)d_in[5];
    const float* fc2b = (const float*)d_in[6];
    const float* ipw  = (const float*)d_in[7];
    const float* cw   = (const float*)d_in[8];
    const float* cb   = (const float*)d_in[9];
    const float* xpw  = (const float*)d_in[10];
    const float* dtw  = (const float*)d_in[11];
    const float* dtb  = (const float*)d_in[12];
    const float* alog = (const float*)d_in[13];
    const float* dsp  = (const float*)d_in[14];
    const float* ong  = (const float*)d_in[15];
    const float* onb  = (const float*)d_in[16];
    const float* opw  = (const float*)d_in[17];
    const float* pw   = (const float*)d_in[18];
    const float* pb   = (const float*)d_in[19];
    const float* skip = (const float*)d_in[20];
    float* out = (float*)d_out;

    cudaFuncSetAttribute(k_gemm_in_mma,  cudaFuncAttributeMaxDynamicSharedMemorySize, GEMM_SMEM3);
    cudaFuncSetAttribute(k_gemm_out_mma, cudaFuncAttributeMaxDynamicSharedMemorySize, GEMM_SMEM3);
    cudaFuncSetAttribute(k_gemm_fin_mma, cudaFuncAttributeMaxDynamicSharedMemorySize, GEMM_SMEM3);

    k_ln1         <<<dim3(32, 8),     128>>>(x, ln_g, ln_b);
    k_roundw      <<<1024,            256>>>(ipw, opw, pw);
    k_zsum        <<<dim3(32, 8),     512>>>();
    k_gemm_in_mma <<<dim3(256, 2, 4), 128, GEMM_SMEM3>>>();
    k_gate        <<<8,               256>>>(fc1w, fc1b, fc2w, fc2b);
    k_conv        <<<dim3(16, 4, 32), 256>>>(cw, cb);
    k_proj        <<<2048,            256>>>(xpw, dtw, dtb, alog);
    k_scanB       <<<32,              128>>>();
    k_scanC_merge <<<dim3(8, 32),     256>>>(dsp, ong, onb);
    k_gemm_out_mma<<<dim3(256, 1, 4), 128, GEMM_SMEM3>>>();
    k_premix      <<<32768,           128>>>(ln_g, ln_b, skip);
    k_gemm_fin_mma<<<dim3(256, 4),    128, GEMM_SMEM3>>>(pb, out);
}

// round 17
// speedup vs baseline: 1.2127x; 1.0027x over previous
#include <cuda_runtime.h>
#include <cuda_fp16.h>
#include <math.h>
#include <stdint.h>

// Problem constants
#define Bsz 8
#define Cch 512
#define Ls 4096
#define Gg 4
#define Dd 128
#define Mrows 32768   // B*L

// ---------------- scratch (device globals; no cudaMalloc allowed) -------------
__device__ __half g_hxn [(size_t)Bsz*Ls*Cch];      // LN1 output (half)
__device__ float  g_zp  [32*Bsz*Cch];
__device__ float  g_gate[Bsz*Cch];
__device__ __half g_hxd [(size_t)Gg*Mrows*Dd];     // in_proj xd half (pre-conv)
__device__ __half g_hz  [(size_t)Gg*Mrows*Dd];     // silu(z) half
__device__ float  g_u   [(size_t)Gg*Mrows*Dd];
__device__ float  g_dA  [(size_t)Gg*Mrows*Dd];
__device__ float  g_dbu [(size_t)Gg*Mrows*Dd];
__device__ float  g_Cv  [Gg*Mrows];
__device__ float  g_P   [Gg*Bsz*64*Dd];
__device__ float  g_hc  [Gg*Bsz*64*Dd];
__device__ float  g_hin [Gg*Bsz*64*Dd];
__device__ __half g_hyz [(size_t)Gg*Mrows*Dd];     // merged LN*z (half)
__device__ float  g_ycat[(size_t)Mrows*Cch];
__device__ __half g_hxmn[(size_t)Mrows*Cch];       // premix output (half)
// fp16-rounded weight copies
__device__ __half g_ipw [Gg*256*128];
__device__ __half g_opw [Gg*128*128];
__device__ __half g_pw  [512*512];

// ---------------- helpers -------------------------------------------------------
__device__ __forceinline__ uint32_t sm_u32(const void* p) {
    return (uint32_t)__cvta_generic_to_shared(p);
}
__device__ __forceinline__ void cpa16(uint32_t dst, const void* src) {
    asm volatile("cp.async.cg.shared.global [%0], [%1], 16;" :: "r"(dst), "l"(src));
}
__device__ __forceinline__ void cpa_commit() { asm volatile("cp.async.commit_group;"); }
template<int N> __device__ __forceinline__ void cpa_wait() {
    asm volatile("cp.async.wait_group %0;" :: "n"(N));
}
__device__ __forceinline__ void mma_f16_16n8k16(float* c, const uint32_t* a, const uint32_t* b) {
    asm volatile(
        "mma.sync.aligned.m16n8k16.row.col.f32.f16.f16.f32 "
        "{%0,%1,%2,%3}, {%4,%5,%6,%7}, {%8,%9}, {%0,%1,%2,%3};"
        : "+f"(c[0]), "+f"(c[1]), "+f"(c[2]), "+f"(c[3])
        : "r"(a[0]), "r"(a[1]), "r"(a[2]), "r"(a[3]), "r"(b[0]), "r"(b[1]));
}
__device__ __forceinline__ void ldsm_x4(uint32_t* r, uint32_t addr) {
    asm volatile("ldmatrix.sync.aligned.m8n8.x4.shared.b16 {%0,%1,%2,%3}, [%4];"
        : "=r"(r[0]), "=r"(r[1]), "=r"(r[2]), "=r"(r[3]) : "r"(addr));
}

// SMEM stage: 128 rows x 32 halves, pitch 40 halves (conflict-free for ldmatrix)
#define SPH 40
#define STAGE_H (128 * SPH)
#define SPAIR_H (2 * STAGE_H)
#define GEMM_SMEM3 (3 * SPAIR_H * 2)   // 61440 bytes

__device__ __forceinline__ void stage_load_h(const __half* __restrict__ g, int ld,
                                             int r0, int k0, __half* sbuf, int tid)
{
#pragma unroll
    for (int i = 0; i < 4; i++) {
        int s = tid + (i << 7);
        int r = s >> 2, seg = s & 3;
        cpa16(sm_u32(sbuf + r * SPH + seg * 8),
              g + (size_t)(r0 + r) * ld + k0 + seg * 8);
    }
}

// ---------------- fp16 mma.sync 128x128xK core (4 warps, 64x64, ldmatrix) -------
template<int S>   // S = K/32 stages
__device__ __forceinline__ void mma_gemm_h(const __half* __restrict__ Ag, int lda,
                                           const __half* __restrict__ Bg,
                                           int mBase, int nBase,
                                           float acc[4][8][4])
{
    extern __shared__ __align__(16) char smraw[];
    __half* hsm = (__half*)smraw;
    const int KTOT = 32 * S;
    int tid = threadIdx.x, wid = tid >> 5, lane = tid & 31;
    int wm = (wid & 1) * 64, wn = (wid >> 1) * 64;

    // per-lane ldmatrix address components (halves)
    int aRow = lane & 15;                       // rows 0..15 within 16-row tile
    int aCol = (lane >> 4) * 8;                 // k +0 / +8
    int bRow = ((lane >> 4) & 1) * 8 + (lane & 7);  // n rows 0..15 within pair
    int bCol = ((lane >> 3) & 1) * 8;           // k +0 / +8
    uint32_t smbase = sm_u32(hsm);

    stage_load_h(Ag, lda, mBase, 0, hsm, tid);
    stage_load_h(Bg, KTOT, nBase, 0, hsm + STAGE_H, tid);
    cpa_commit();
    if (S > 1) {
        stage_load_h(Ag, lda, mBase, 32, hsm + SPAIR_H, tid);
        stage_load_h(Bg, KTOT, nBase, 32, hsm + SPAIR_H + STAGE_H, tid);
    }
    cpa_commit();

    int sslot = 0;
    for (int s = 0; s < S; s++) {
        if (s + 1 < S) cpa_wait<1>(); else cpa_wait<0>();
        __syncthreads();
        if (s + 2 < S) {
            int ns = sslot + 2; if (ns >= 3) ns -= 3;
            __half* nb = hsm + ns * SPAIR_H;
            stage_load_h(Ag, lda, mBase, (s + 2) * 32, nb, tid);
            stage_load_h(Bg, KTOT, nBase, (s + 2) * 32, nb + STAGE_H, tid);
            cpa_commit();
        } else {
            cpa_commit();
        }
        uint32_t Ab = smbase + (uint32_t)(sslot * SPAIR_H) * 2u;
        uint32_t Bb = Ab + (uint32_t)STAGE_H * 2u;
#pragma unroll
        for (int ks = 0; ks < 2; ks++) {
            uint32_t afr[4][4];
#pragma unroll
            for (int mt = 0; mt < 4; mt++)
                ldsm_x4(afr[mt],
                        Ab + (uint32_t)(((wm + mt * 16 + aRow) * SPH + ks * 16 + aCol) * 2));
#pragma unroll
            for (int p = 0; p < 4; p++) {
                uint32_t bfr[4];
                ldsm_x4(bfr,
                        Bb + (uint32_t)(((wn + p * 16 + bRow) * SPH + ks * 16 + bCol) * 2));
#pragma unroll
                for (int mt = 0; mt < 4; mt++) {
                    mma_f16_16n8k16(acc[mt][2 * p],     afr[mt], bfr);
                    mma_f16_16n8k16(acc[mt][2 * p + 1], afr[mt], bfr + 2);
                }
            }
        }
        if (++sslot == 3) sslot = 0;
    }
}

// ---------------- kernel 1: layernorm over C (writes half) ---------------------
__global__ void k_ln1(const float* __restrict__ x,
                      const float* __restrict__ lg, const float* __restrict__ lb)
{
    int b = blockIdx.y;
    int l = blockIdx.x * 128 + threadIdx.x;
    const float* xp = x + (size_t)b * Cch * Ls + l;
    float s = 0.f, s2 = 0.f;
#pragma unroll 8
    for (int c = 0; c < Cch; c++) { float v = xp[(size_t)c * Ls]; s += v; s2 += v * v; }
    float mu = s * (1.f / Cch);
    float rs = rsqrtf(s2 * (1.f / Cch) - mu * mu + 1e-5f);
    __half* out = g_hxn + ((size_t)b * Ls + l) * Cch;
#pragma unroll 4
    for (int c = 0; c < Cch; c += 4) {
        float v0 = (xp[(size_t)(c + 0) * Ls] - mu) * rs * lg[c + 0] + lb[c + 0];
        float v1 = (xp[(size_t)(c + 1) * Ls] - mu) * rs * lg[c + 1] + lb[c + 1];
        float v2 = (xp[(size_t)(c + 2) * Ls] - mu) * rs * lg[c + 2] + lb[c + 2];
        float v3 = (xp[(size_t)(c + 3) * Ls] - mu) * rs * lg[c + 3] + lb[c + 3];
        *(__half2*)(out + c)     = __floats2half2_rn(v0, v1);
        *(__half2*)(out + c + 2) = __floats2half2_rn(v2, v3);
    }
}

// ---------------- kernel 2: partial column sums -------------------------------
__global__ void k_zsum()
{
    int b = blockIdx.y, k = blockIdx.x, c = threadIdx.x;
    const __half* p = g_hxn + ((size_t)b * Ls + k * 128) * Cch + c;
    float s = 0.f;
#pragma unroll 8
    for (int i = 0; i < 128; i++) s += __half2float(p[(size_t)i * Cch]);
    g_zp[(k * Bsz + b) * Cch + c] = s;
}

// ---------------- kernel 3: gate MLP (one block per batch) ---------------------
__global__ void __launch_bounds__(256) k_gate(const float* __restrict__ fc1w,
                                              const float* __restrict__ fc1b,
                                              const float* __restrict__ fc2w,
                                              const float* __restrict__ fc2b)
{
    __shared__ float zsm[512];
    __shared__ float hsm[32];
    int t = threadIdx.x, b = blockIdx.x;
    int warp = t >> 5, lane = t & 31;
    for (int c = t; c < 512; c += 256) {
        float s = 0.f;
#pragma unroll
        for (int k = 0; k < 32; k++) s += g_zp[(k * Bsz + b) * 512 + c];
        zsm[c] = s * (1.f / Ls);
    }
    __syncthreads();
    for (int r = warp; r < 32; r += 8) {
        float p = 0.f;
#pragma unroll 4
        for (int i = lane; i < 512; i += 32) p += zsm[i] * fc1w[r * 512 + i];
#pragma unroll
        for (int o = 16; o; o >>= 1) p += __shfl_xor_sync(0xffffffffu, p, o);
        if (lane == 0) hsm[r] = fmaxf(p + fc1b[r], 0.f);
    }
    __syncthreads();
    for (int c = t; c < 512; c += 256) {
        float s = fc2b[c];
#pragma unroll
        for (int r = 0; r < 32; r++) s += hsm[r] * fc2w[c * 32 + r];
        g_gate[b * 512 + c] = 1.f / (1.f + expf(-s));
    }
}

// ---------------- weight rounding (fp16 RNE) ------------------------------------
__global__ void k_roundw(const float* __restrict__ ipw, const float* __restrict__ opw,
                         const float* __restrict__ pw)
{
    int i = blockIdx.x * 256 + threadIdx.x;
    if (i < Gg * 256 * 128) g_ipw[i] = __float2half_rn(ipw[i]);
    if (i < Gg * 128 * 128) g_opw[i] = __float2half_rn(opw[i]);
    if (i < 512 * 512)      g_pw[i]  = __float2half_rn(pw[i]);
}

// ---------------- GEMM 1: in_proj (xd half / silu(z) half) ----------------------
__global__ void __launch_bounds__(128) k_gemm_in_mma()
{
    int g = blockIdx.z;
    int mBase = blockIdx.x * 128, nBase = blockIdx.y * 128;
    float acc[4][8][4] = {};
    mma_gemm_h<4>(g_hxn + g * 128, Cch, g_ipw + (size_t)g * 256 * 128,
                  mBase, nBase, acc);
    int lane = threadIdx.x & 31, wid = threadIdx.x >> 5;
    int gid = lane >> 2, tidx = lane & 3;
    int wm = (wid & 1) * 64, wn = (wid >> 1) * 64;
    bool dosilu = (nBase >= 128);
    __half* Cp = (dosilu ? g_hz : g_hxd) + (size_t)g * Mrows * 128;
#pragma unroll
    for (int mt = 0; mt < 4; mt++)
#pragma unroll
    for (int half = 0; half < 2; half++) {
        int m = mBase + wm + mt * 16 + gid + half * 8;
        __half* dst = Cp + (size_t)m * 128 + wn + 2 * tidx;
#pragma unroll
        for (int nt = 0; nt < 8; nt++) {
            float v0 = acc[mt][nt][half * 2], v1 = acc[mt][nt][half * 2 + 1];
            if (dosilu) { v0 = v0 / (1.f + expf(-v0)); v1 = v1 / (1.f + expf(-v1)); }
            *(__half2*)(dst + nt * 8) = __floats2half2_rn(v0, v1);
        }
    }
}

// ---------------- GEMM 2: out_proj ----------------------------------------------
__global__ void __launch_bounds__(128) k_gemm_out_mma()
{
    int g = blockIdx.z;
    int mBase = blockIdx.x * 128;
    float acc[4][8][4] = {};
    mma_gemm_h<4>(g_hyz + (size_t)g * Mrows * 128, 128, g_opw + (size_t)g * 128 * 128,
                  mBase, 0, acc);
    int lane = threadIdx.x & 31, wid = threadIdx.x >> 5;
    int gid = lane >> 2, tidx = lane & 3;
    int wm = (wid & 1) * 64, wn = (wid >> 1) * 64;
#pragma unroll
    for (int mt = 0; mt < 4; mt++)
#pragma unroll
    for (int half = 0; half < 2; half++) {
        int m = mBase + wm + mt * 16 + gid + half * 8;
        float* dst = g_ycat + (size_t)m * 512 + g * 128 + wn + 2 * tidx;
#pragma unroll
        for (int nt = 0; nt < 8; nt++) {
            float2 o = { acc[mt][nt][half * 2], acc[mt][nt][half * 2 + 1] };
            *(float2*)(dst + nt * 8) = o;
        }
    }
}

// ---------------- GEMM 3: final proj (transposed store + bias) -------------------
__global__ void __launch_bounds__(128) k_gemm_fin_mma(const float* __restrict__ pb,
                                                      float* __restrict__ out)
{
    int mBase = blockIdx.x * 128, nBase = blockIdx.y * 128;
    float acc[4][8][4] = {};
    mma_gemm_h<16>(g_hxmn, 512, g_pw, mBase, nBase, acc);
    int lane = threadIdx.x & 31, wid = threadIdx.x >> 5;
    int gid = lane >> 2, tidx = lane & 3;
    int wm = (wid & 1) * 64, wn = (wid >> 1) * 64;
#pragma unroll
    for (int mt = 0; mt < 4; mt++)
#pragma unroll
    for (int half = 0; half < 2; half++) {
        int m = mBase + wm + mt * 16 + gid + half * 8;
        int b = m >> 12, l = m & 4095;
#pragma unroll
        for (int nt = 0; nt < 8; nt++) {
            int n = nBase + wn + nt * 8 + 2 * tidx;
            out[((size_t)(b * 512 + n)) * 4096 + l]     = acc[mt][nt][half * 2]     + __ldg(pb + n);
            out[((size_t)(b * 512 + n + 1)) * 4096 + l] = acc[mt][nt][half * 2 + 1] + __ldg(pb + n + 1);
        }
    }
}

// ---------------- kernel 5: depthwise conv + silu + cross_scan -----------------
__global__ void __launch_bounds__(256) k_conv(const float* __restrict__ cw,
                                              const float* __restrict__ cb)
{
    __shared__ float sx[324 * 32];
    __shared__ float wsm[32 * 9];
    __shared__ float bsm[32];
    int tile = blockIdx.x, dt = blockIdx.y, gb = blockIdx.z;
    int g = gb >> 3, b = gb & 7;
    int h0 = (tile >> 2) * 16, w0 = (tile & 3) * 16;
    int dbase = dt * 32;
    int tid = threadIdx.x;
    const __half* src = g_hxd + ((size_t)g * Mrows + b * Ls) * 128;
    for (int idx = tid; idx < 324 * 32; idx += 256) {
        int pos = idx >> 5, dd = idx & 31;
        int h = h0 + pos / 18 - 1, w = w0 + pos % 18 - 1;
        float v = 0.f;
        if (h >= 0 && h < 64 && w >= 0 && w < 64)
            v = __half2float(src[(size_t)(h * 64 + w) * 128 + dbase + dd]);
        sx[idx] = v;
    }
    for (int i = tid; i < 288; i += 256)
        wsm[i] = cw[(size_t)(g * 128 + dbase + i / 9) * 9 + i % 9];
    if (tid < 32)  bsm[tid] = cb[g * 128 + dbase + tid];
    __syncthreads();
    int dd = tid & 31;
    float* dstbase = g_u + ((size_t)g * Mrows + b * Ls) * 128 + dbase + dd;
#pragma unroll 4
    for (int it = 0; it < 32; it++) {
        int pos = it * 8 + (tid >> 5);
        int ph = pos >> 4, pw = pos & 15;
        float acc = bsm[dd];
#pragma unroll
        for (int kh = 0; kh < 3; kh++)
#pragma unroll
            for (int kw = 0; kw < 3; kw++)
                acc += sx[((ph + kh) * 18 + pw + kw) * 32 + dd] * wsm[dd * 9 + kh * 3 + kw];
        acc = acc / (1.f + expf(-acc));
        int h = h0 + ph, w = w0 + pw;
        int lp;
        if (g == 0)      lp = h * 64 + w;
        else if (g == 1) lp = w * 64 + h;
        else if (g == 2) lp = 4095 - (h * 64 + w);
        else             lp = 4095 - (w * 64 + h);
        dstbase[(size_t)lp * 128] = acc;
    }
}

// ---------------- kernel 6: x_proj + dt_proj + dA/dBu/C + chunk scan summary ---
__global__ void __launch_bounds__(256) k_proj(const float* __restrict__ xpw,
                                              const float* __restrict__ dtw_g,
                                              const float* __restrict__ dtb_g,
                                              const float* __restrict__ alog)
{
    __shared__ float xp[10 * 128];
    __shared__ float dtwT[8 * 128];
    __shared__ float dtb[128];
    __shared__ float An[128];
    __shared__ float sP[8][128], sH[8][128];
    int tid = threadIdx.x, lane = tid & 31, warp = tid >> 5;
    int chunk0 = blockIdx.x * 8;
    int g = chunk0 >> 12;
    for (int i = tid; i < 1280; i += 256) xp[i] = xpw[(size_t)g * 1280 + i];
    for (int i = tid; i < 1024; i += 256) {
        int r = i >> 7, d = i & 127;
        dtwT[i] = dtw_g[(size_t)(g * 128 + d) * 8 + r];
    }
    if (tid < 128) { dtb[tid] = dtb_g[g * 128 + tid]; An[tid] = -expf(alog[g * 128 + tid]); }
    __syncthreads();
    int chunk = chunk0 + warp;
    int b = (chunk >> 9) & 7;
    int lp0 = (chunk & 511) * 8;
    size_t rowbase = (size_t)(g * 8 + b) * 4096 + lp0;
    float hseg[4] = {0.f, 0.f, 0.f, 0.f};
    float Pseg[4] = {1.f, 1.f, 1.f, 1.f};
    for (int it = 0; it < 8; it++) {
        size_t row = rowbase + it;
        float4 u4 = *(const float4*)(g_u + row * 128 + lane * 4);
        float xdbl[10];
#pragma unroll
        for (int c = 0; c < 10; c++) {
            const float* xc = xp + c * 128 + lane * 4;
            float p = u4.x * xc[0] + u4.y * xc[1] + u4.z * xc[2] + u4.w * xc[3];
#pragma unroll
            for (int o = 16; o; o >>= 1) p += __shfl_xor_sync(0xffffffffu, p, o);
            xdbl[c] = p;
        }
        float Bm = xdbl[8];
        float uarr[4] = { u4.x, u4.y, u4.z, u4.w };
        float dA4[4], db4[4];
#pragma unroll
        for (int j = 0; j < 4; j++) {
            int d = lane * 4 + j;
            float s = dtb[d];
#pragma unroll
            for (int r = 0; r < 8; r++) s += xdbl[r] * dtwT[r * 128 + d];
            float delta = (s > 20.f) ? s : log1pf(expf(s));
            dA4[j] = expf(delta * An[d]);
            db4[j] = delta * uarr[j] * Bm;
            hseg[j] = fmaf(dA4[j], hseg[j], db4[j]);
            Pseg[j] *= dA4[j];
        }
        *(float4*)(g_dA  + row * 128 + lane * 4) = *(float4*)dA4;
        *(float4*)(g_dbu + row * 128 + lane * 4) = *(float4*)db4;
        if (lane == 0) g_Cv[row] = xdbl[9];
    }
#pragma unroll
    for (int j = 0; j < 4; j++) { sP[warp][lane * 4 + j] = Pseg[j]; sH[warp][lane * 4 + j] = hseg[j]; }
    __syncthreads();
    if (tid < 128) {
        int d = tid;
        float h = 0.f, P = 1.f;
#pragma unroll
        for (int w = 0; w < 8; w++) {
            h = fmaf(sP[w][d], h, sH[w][d]);
            P *= sP[w][d];
        }
        int gb = g * 8 + b;
        int ch = (chunk0 & 511) >> 3;
        size_t o = ((size_t)gb * 64 + ch) * 128 + d;
        g_P[o] = P; g_hc[o] = h;
    }
}

// ---------------- kernel 7: inter-chunk serial scan ------------------------------
__global__ void k_scanB()
{
    int gb = blockIdx.x, d = threadIdx.x;
    float h = 0.f;
    for (int ch = 0; ch < 64; ch++) {
        size_t o = ((size_t)gb * 64 + ch) * 128 + d;
        g_hin[o] = h;
        h = fmaf(g_P[o], h, g_hc[o]);
    }
}

// ---------------- kernel 8: scanC + merge, WARP-PER-CHUNK (no block barriers) ---
__global__ void __launch_bounds__(256) k_scanC_merge(const float* __restrict__ Dsp,
                                                     const float* __restrict__ og_,
                                                     const float* __restrict__ ob_)
{
    int gb = blockIdx.y;
    int warp = threadIdx.x >> 5, lane = threadIdx.x & 31;
    int chunk = blockIdx.x * 8 + warp;
    int g = gb >> 3;
    int d0 = lane * 4;
    float4 Ds4 = *(const float4*)(Dsp + g * 128 + d0);
    float4 og4 = *(const float4*)(og_ + g * 128 + d0);
    float4 ob4 = *(const float4*)(ob_ + g * 128 + d0);
    float Ds[4] = { Ds4.x, Ds4.y, Ds4.z, Ds4.w };
    float og[4] = { og4.x, og4.y, og4.z, og4.w };
    float ob[4] = { ob4.x, ob4.y, ob4.z, ob4.w };
    float4 h4 = *(const float4*)(g_hin + ((size_t)gb * 64 + chunk) * 128 + d0);
    float h[4] = { h4.x, h4.y, h4.z, h4.w };
    size_t base = ((size_t)gb * 4096 + chunk * 64) * 128 + d0;
    size_t crow = (size_t)gb * 4096 + chunk * 64;
#pragma unroll 2
    for (int i = 0; i < 64; i++) {
        size_t idx = base + (size_t)i * 128;
        float4 a4 = *(const float4*)(g_dA  + idx);
        float4 b4 = *(const float4*)(g_dbu + idx);
        float4 u4 = *(const float4*)(g_u   + idx);
        float Cv = g_Cv[crow + i];
        h[0] = fmaf(a4.x, h[0], b4.x);
        h[1] = fmaf(a4.y, h[1], b4.y);
        h[2] = fmaf(a4.z, h[2], b4.z);
        h[3] = fmaf(a4.w, h[3], b4.w);
        float yv[4] = { h[0] * Cv + Ds[0] * u4.x, h[1] * Cv + Ds[1] * u4.y,
                        h[2] * Cv + Ds[2] * u4.z, h[3] * Cv + Ds[3] * u4.w };
        float s = yv[0] + yv[1] + yv[2] + yv[3];
        float q = yv[0] * yv[0] + yv[1] * yv[1] + yv[2] * yv[2] + yv[3] * yv[3];
#pragma unroll
        for (int o = 16; o; o >>= 1) {
            s += __shfl_xor_sync(0xffffffffu, s, o);
            q += __shfl_xor_sync(0xffffffffu, q, o);
        }
        float mu = s * (1.f / 128.f);
        float rs = rsqrtf(q * (1.f / 128.f) - mu * mu + 1e-5f);
        int lp = chunk * 64 + i;
        int l;
        if (g == 0)      l = lp;
        else if (g == 1) l = (lp & 63) * 64 + (lp >> 6);
        else if (g == 2) l = 4095 - lp;
        else { int t2 = 4095 - lp; l = (t2 & 63) * 64 + (t2 >> 6); }
        size_t drow = (size_t)gb * 4096 + l;
        const __half2* zp = (const __half2*)(g_hz + drow * 128 + d0);
        float2 zA = __half22float2(zp[0]);
        float2 zB = __half22float2(zp[1]);
        __half2 o01 = __floats2half2_rn(((yv[0] - mu) * rs * og[0] + ob[0]) * zA.x,
                                        ((yv[1] - mu) * rs * og[1] + ob[1]) * zA.y);
        __half2 o23 = __floats2half2_rn(((yv[2] - mu) * rs * og[2] + ob[2]) * zB.x,
                                        ((yv[3] - mu) * rs * og[3] + ob[3]) * zB.y);
        __half2* outp = (__half2*)(g_hyz + drow * 128 + d0);
        outp[0] = o01; outp[1] = o23;
    }
}

// ---------------- kernel 12: mix + gate + LN(C) ---------------------------------
__global__ void __launch_bounds__(128) k_premix(const float* __restrict__ lg,
                                                const float* __restrict__ lb,
                                                const float* __restrict__ skip)
{
    int row = blockIdx.x, b = row >> 12, tid = threadIdx.x;
    float sk = skip[0];
    float4 yc = *(const float4*)(g_ycat + (size_t)row * 512 + tid * 4);
    const __half2* xnp = (const __half2*)(g_hxn + (size_t)row * 512 + tid * 4);
    float2 x01 = __half22float2(xnp[0]);
    float2 x23 = __half22float2(xnp[1]);
    float4 gt = *(const float4*)(g_gate + (size_t)b * 512 + tid * 4);
    float v[4] = { yc.x * sk * x01.x * gt.x, yc.y * sk * x01.y * gt.y,
                   yc.z * sk * x23.x * gt.z, yc.w * sk * x23.y * gt.w };
    float s  = v[0] + v[1] + v[2] + v[3];
    float s2 = v[0] * v[0] + v[1] * v[1] + v[2] * v[2] + v[3] * v[3];
#pragma unroll
    for (int o = 16; o; o >>= 1) {
        s  += __shfl_xor_sync(0xffffffffu, s, o);
        s2 += __shfl_xor_sync(0xffffffffu, s2, o);
    }
    __shared__ float rs_[4], rq_[4];
    int warp = tid >> 5, lane = tid & 31;
    if (lane == 0) { rs_[warp] = s; rq_[warp] = s2; }
    __syncthreads();
    s  = rs_[0] + rs_[1] + rs_[2] + rs_[3];
    s2 = rq_[0] + rq_[1] + rq_[2] + rq_[3];
    float mu = s * (1.f / 512.f);
    float rstd = rsqrtf(s2 * (1.f / 512.f) - mu * mu + 1e-5f);
    __half2 o01 = __floats2half2_rn((v[0] - mu) * rstd * lg[tid * 4 + 0] + lb[tid * 4 + 0],
                                    (v[1] - mu) * rstd * lg[tid * 4 + 1] + lb[tid * 4 + 1]);
    __half2 o23 = __floats2half2_rn((v[2] - mu) * rstd * lg[tid * 4 + 2] + lb[tid * 4 + 2],
                                    (v[3] - mu) * rstd * lg[tid * 4 + 3] + lb[tid * 4 + 3]);
    __half2* outp = (__half2*)(g_hxmn + (size_t)row * 512 + tid * 4);
    outp[0] = o01; outp[1] = o23;
}

// ---------------- launch ---------------------------------------------------------
extern "C" void kernel_launch(void* const* d_in, const int* in_sizes, int n_in,
                              void* d_out, int out_size)
{
    const float* x    = (const float*)d_in[0];
    const float* ln_g = (const float*)d_in[1];
    const float* ln_b = (const float*)d_in[2];
    const float* fc1w = (const float*)d_in[3];
    const float* fc1b = (const float*)d_in[4];
    const float* fc2w = (const float*)d_in[5];
    const float* fc2b = (const float*)d_in[6];
    const float* ipw  = (const float*)d_in[7];
    const float* cw   = (const float*)d_in[8];
    const float* cb   = (const float*)d_in[9];
    const float* xpw  = (const float*)d_in[10];
    const float* dtw  = (const float*)d_in[11];
    const float* dtb  = (const float*)d_in[12];
    const float* alog = (const float*)d_in[13];
    const float* dsp  = (const float*)d_in[14];
    const float* ong  = (const float*)d_in[15];
    const float* onb  = (const float*)d_in[16];
    const float* opw  = (const float*)d_in[17];
    const float* pw   = (const float*)d_in[18];
    const float* pb   = (const float*)d_in[19];
    const float* skip = (const float*)d_in[20];
    float* out = (float*)d_out;

    cudaFuncSetAttribute(k_gemm_in_mma,  cudaFuncAttributeMaxDynamicSharedMemorySize, GEMM_SMEM3);
    cudaFuncSetAttribute(k_gemm_out_mma, cudaFuncAttributeMaxDynamicSharedMemorySize, GEMM_SMEM3);
    cudaFuncSetAttribute(k_gemm_fin_mma, cudaFuncAttributeMaxDynamicSharedMemorySize, GEMM_SMEM3);

    k_ln1         <<<dim3(32, 8),     128>>>(x, ln_g, ln_b);
    k_roundw      <<<1024,            256>>>(ipw, opw, pw);
    k_zsum        <<<dim3(32, 8),     512>>>();
    k_gemm_in_mma <<<dim3(256, 2, 4), 128, GEMM_SMEM3>>>();
    k_gate        <<<8,               256>>>(fc1w, fc1b, fc2w, fc2b);
    k_conv        <<<dim3(16, 4, 32), 256>>>(cw, cb);
    k_proj        <<<2048,            256>>>(xpw, dtw, dtb, alog);
    k_scanB       <<<32,              128>>>();
    k_scanC_merge <<<dim3(8, 32),     256>>>(dsp, ong, onb);
    k_gemm_out_mma<<<dim3(256, 1, 4), 128, GEMM_SMEM3>>>();
    k_premix      <<<32768,           128>>>(ln_g, ln_b, skip);
    k_gemm_fin_mma<<<dim3(256, 4),    128, GEMM_SMEM3>>>(pb, out);
}